// round 4
// baseline (speedup 1.0000x reference)
#include <cuda_runtime.h>
#include <math.h>
#include <cstdint>

// Problem constants
#define B_    4
#define H_    128
#define W_    128
#define C_    256
#define NH_   8
#define HD_   32
#define HW_   (H_ * W_)                 // 16384
#define NWIN  (B_ * H_)                 // 512
#define NCTA  (NWIN * NH_)              // 4096
#define QKV_STRIDE ((size_t)B_ * HW_ * C_)

// Scratch: ungated attention output y = (1-cos(...)) @ V  (67 MB fp32)
__device__ float g_y[(size_t)B_ * HW_ * C_];
__device__ float g_wsum[NWIN];
__device__ float g_M[NWIN];

// ---------------- packed f32x2 FMA helpers ----------------
#define FFMA2(d, a, b) \
    asm volatile("fma.rn.f32x2 %0, %1, %2, %0;" : "+l"(d) : "l"(a), "l"(b))
#define BCAST2(d, x) \
    asm volatile("mov.b64 %0, {%1, %1};" : "=l"(d) : "r"(__float_as_uint(x)))
#define UNPK2(lo, hi, v) \
    asm volatile("mov.b64 {%0, %1}, %2;" : "=r"(lo), "=r"(hi) : "l"(v))

// ---------------- fused kernel smem layout (float offsets) ----------------
// Phase 1 (QK):   Qs[32][132] @ 0,  Ks[32][132] @ 4224   (inside As region)
// Phase 2 (AV):   As[128][132] @ 0
// Always:         Vs[128][32] @ 16896,  magt[256] @ 20992,  wsum[8] @ 21248
#define QS_F       0
#define KS_F       4224
#define AS_F       0
#define AS_STRIDE  132
#define VS_F       16896
#define MAGT_F     20992
#define WS_F       21248
#define SMEM_FLOATS 21256
#define FUSED_SMEM (SMEM_FLOATS * 4)   // 85,024 bytes

// ---------------------------------------------------------------------------
// Fused kernel: per (window, head):
//   1. stage Q/K transposed [d][w] + V [w][d] into smem
//   2. QK^T via FFMA2 (8x8 tile/thread) -> registers
//   3. +RPE bias, per-window |.| sums (atomicAdd), per-row L2 norm,
//      1 - cos(v * pi/2 / norm)  -> As   (gate M deferred to blend kernel)
//   4. As @ V via FFMA2 -> g_y (ungated)
// ---------------------------------------------------------------------------
__global__ __launch_bounds__(256, 2) void fused_kernel(const float* __restrict__ qkv) {
    extern __shared__ float sm[];

    const int bx  = blockIdx.x;        // 0..4095
    const int wi  = bx >> 3;           // window
    const int n   = bx & 7;            // head
    const int b   = wi >> 7;
    const int h   = wi & 127;
    const int tid = threadIdx.x;

    // RPE magnitude table: delta(q,k) = (k - q) * 2*pi/127
    if (tid < 255) {
        float delta = (float)(tid - 127) * (6.283185307179586477f / 127.0f);
        sm[MAGT_F + tid] = sqrtf(fmaxf(2.0f - 2.0f * cosf(delta), 0.0f));
    }

    // Stage Q, K transposed ([d][w], stride 132) and V plain ([w][d])
    const float* qb = qkv + ((size_t)(b * HW_) + (size_t)h * W_) * C_ + n * HD_;
    const float* kb = qb + QKV_STRIDE;
    const float* vb = kb + QKV_STRIDE;
    #pragma unroll
    for (int t = 0; t < 4; ++t) {
        int idx = tid + t * 256;       // 1024 float4 chunks
        int w   = idx >> 3;            // row 0..127
        int d4  = (idx & 7) << 2;      // 0,4,...,28
        float4 qv = *(const float4*)(qb + (size_t)w * C_ + d4);
        float4 kv = *(const float4*)(kb + (size_t)w * C_ + d4);
        float4 vv = *(const float4*)(vb + (size_t)w * C_ + d4);
        sm[QS_F + (d4 + 0) * 132 + w] = qv.x;
        sm[QS_F + (d4 + 1) * 132 + w] = qv.y;
        sm[QS_F + (d4 + 2) * 132 + w] = qv.z;
        sm[QS_F + (d4 + 3) * 132 + w] = qv.w;
        sm[KS_F + (d4 + 0) * 132 + w] = kv.x;
        sm[KS_F + (d4 + 1) * 132 + w] = kv.y;
        sm[KS_F + (d4 + 2) * 132 + w] = kv.z;
        sm[KS_F + (d4 + 3) * 132 + w] = kv.w;
        *(float4*)(sm + VS_F + w * 32 + d4) = vv;
    }
    __syncthreads();

    // ---- QK^T: 8x8 tile per thread, FFMA2 pairs along k ----
    const int kx = tid & 15;
    const int qy = tid >> 4;
    const int q0 = qy << 3;
    const int k0 = kx << 3;

    unsigned long long acc2[8][4];
    #pragma unroll
    for (int i = 0; i < 8; ++i)
        #pragma unroll
        for (int j = 0; j < 4; ++j) acc2[i][j] = 0ULL;

    #pragma unroll 4
    for (int kk = 0; kk < 32; ++kk) {
        float4 a0 = *(const float4*)(sm + QS_F + kk * 132 + q0);
        float4 a1 = *(const float4*)(sm + QS_F + kk * 132 + q0 + 4);
        ulonglong2 bA = *(const ulonglong2*)(sm + KS_F + kk * 132 + k0);
        ulonglong2 bB = *(const ulonglong2*)(sm + KS_F + kk * 132 + k0 + 4);
        const unsigned long long bb0 = bA.x, bb1 = bA.y, bb2 = bB.x, bb3 = bB.y;
        float af[8] = {a0.x, a0.y, a0.z, a0.w, a1.x, a1.y, a1.z, a1.w};
        #pragma unroll
        for (int i = 0; i < 8; ++i) {
            unsigned long long ad;
            BCAST2(ad, af[i]);
            FFMA2(acc2[i][0], ad, bb0);
            FFMA2(acc2[i][1], ad, bb1);
            FFMA2(acc2[i][2], ad, bb2);
            FFMA2(acc2[i][3], ad, bb3);
        }
    }

    // ---- bias + |.| accumulation + row sum-of-squares ----
    const float bscale = 0.1f * sinf((float)h * (3.14159265358979323846f / 128.0f));
    float vals[8][8];
    float ss[8];
    float s_abs = 0.0f;
    #pragma unroll
    for (int i = 0; i < 8; ++i) {
        const int q = q0 + i;
        float s_sq = 0.0f;
        #pragma unroll
        for (int j2 = 0; j2 < 4; ++j2) {
            unsigned int lo, hi;
            UNPK2(lo, hi, acc2[i][j2]);
            float v0, v1;
            {
                const int k = k0 + 2 * j2;
                float bias = ((k > q) ? bscale : -bscale) * sm[MAGT_F + (k - q + 127)];
                v0 = __uint_as_float(lo) + bias;
            }
            {
                const int k = k0 + 2 * j2 + 1;
                float bias = ((k > q) ? bscale : -bscale) * sm[MAGT_F + (k - q + 127)];
                v1 = __uint_as_float(hi) + bias;
            }
            vals[i][2 * j2]     = v0;
            vals[i][2 * j2 + 1] = v1;
            s_abs += fabsf(v0) + fabsf(v1);
            s_sq  += v0 * v0 + v1 * v1;
        }
        ss[i] = s_sq;
    }

    // per-window |attn| sum
    #pragma unroll
    for (int m = 16; m; m >>= 1)
        s_abs += __shfl_xor_sync(0xffffffffu, s_abs, m);
    if ((tid & 31) == 0) sm[WS_F + (tid >> 5)] = s_abs;

    // row sum-of-squares across the 16 kx lanes (xor<=8 stays in-group)
    #pragma unroll
    for (int m = 1; m < 16; m <<= 1)
        #pragma unroll
        for (int i = 0; i < 8; ++i)
            ss[i] += __shfl_xor_sync(0xffffffffu, ss[i], m);

    __syncthreads();   // WS_F written; Qs/Ks reads done -> As may be overwritten

    if (tid == 0) {
        float s = 0.0f;
        #pragma unroll
        for (int i = 0; i < 8; ++i) s += sm[WS_F + i];
        atomicAdd(&g_wsum[wi], s);
    }

    // ---- transform: 1 - cos(v * (pi/2)/norm)  (no M) -> As ----
    #pragma unroll
    for (int i = 0; i < 8; ++i) {
        float inv = 1.57079632679489662f / fmaxf(sqrtf(ss[i]), 1e-12f);
        __align__(16) float row[8];
        #pragma unroll
        for (int j = 0; j < 8; ++j)
            row[j] = 1.0f - __cosf(vals[i][j] * inv);
        *(float4*)(sm + AS_F + (q0 + i) * AS_STRIDE + k0)     = *(float4*)(row);
        *(float4*)(sm + AS_F + (q0 + i) * AS_STRIDE + k0 + 4) = *(float4*)(row + 4);
    }
    __syncthreads();

    // ---- AV GEMM: y[128 q][32 d] = As @ V, 4x4 thread tile, FFMA2 along d ----
    const int qg = (tid >> 3) << 2;   // 0..124
    const int dg = (tid & 7) << 2;    // 0..28
    unsigned long long oacc[4][2];
    #pragma unroll
    for (int i = 0; i < 4; ++i) { oacc[i][0] = 0ULL; oacc[i][1] = 0ULL; }

    #pragma unroll 4
    for (int kkb = 0; kkb < 128; kkb += 4) {
        __align__(16) float aa[4][4];
        #pragma unroll
        for (int i = 0; i < 4; ++i)
            *(float4*)(aa[i]) = *(const float4*)(sm + AS_F + (qg + i) * AS_STRIDE + kkb);
        #pragma unroll
        for (int t = 0; t < 4; ++t) {
            ulonglong2 bv = *(const ulonglong2*)(sm + VS_F + (kkb + t) * 32 + dg);
            #pragma unroll
            for (int i = 0; i < 4; ++i) {
                unsigned long long ad;
                BCAST2(ad, aa[i][t]);
                FFMA2(oacc[i][0], ad, bv.x);
                FFMA2(oacc[i][1], ad, bv.y);
            }
        }
    }

    const size_t obase = ((size_t)(b * HW_) + (size_t)h * W_) * C_ + n * HD_;
    #pragma unroll
    for (int i = 0; i < 4; ++i) {
        unsigned int lo, hi;
        __align__(16) float o[4];
        UNPK2(lo, hi, oacc[i][0]);
        o[0] = __uint_as_float(lo); o[1] = __uint_as_float(hi);
        UNPK2(lo, hi, oacc[i][1]);
        o[2] = __uint_as_float(lo); o[3] = __uint_as_float(hi);
        *(float4*)(g_y + obase + (size_t)(qg + i) * C_ + dg) = *(float4*)o;
    }
}

// ---------------------------------------------------------------------------
// Gate: mean |attn| per window, global max, M = max(mean/max, 0.5).
// Resets g_wsum for the next graph replay.
// ---------------------------------------------------------------------------
__global__ void gate_kernel() {
    __shared__ float red[512];
    const int t = threadIdx.x;
    float mean = g_wsum[t] * (1.0f / 131072.0f);   // / (NH*W*W)
    g_wsum[t] = 0.0f;
    red[t] = mean;
    __syncthreads();
    for (int s = 256; s > 0; s >>= 1) {
        if (t < s) red[t] = fmaxf(red[t], red[t + s]);
        __syncthreads();
    }
    g_M[t] = fmaxf(mean / red[0], 0.5f);
}

// ---------------------------------------------------------------------------
// Blend: out = M * y + (1 - M) * res   (pure bandwidth, float4)
// ---------------------------------------------------------------------------
__global__ __launch_bounds__(256) void blend_kernel(const float* __restrict__ resx,
                                                    float* __restrict__ out) {
    const int i  = blockIdx.x * 256 + threadIdx.x;   // float4 index
    const int wi = i >> 13;                          // / (W_*C_/4 = 8192)
    const float Mw   = g_M[wi];
    const float oneM = 1.0f - Mw;
    float4 y = ((const float4*)g_y)[i];
    float4 r = ((const float4*)resx)[i];
    float4 o;
    o.x = fmaf(Mw, y.x, oneM * r.x);
    o.y = fmaf(Mw, y.y, oneM * r.y);
    o.z = fmaf(Mw, y.z, oneM * r.z);
    o.w = fmaf(Mw, y.w, oneM * r.w);
    ((float4*)out)[i] = o;
}

// ---------------------------------------------------------------------------
extern "C" void kernel_launch(void* const* d_in, const int* in_sizes, int n_in,
                              void* d_out, int out_size) {
    (void)in_sizes; (void)n_in; (void)out_size;
    const float* qkv  = (const float*)d_in[0];
    const float* resx = (const float*)d_in[1];
    float* out = (float*)d_out;

    cudaFuncSetAttribute(fused_kernel, cudaFuncAttributeMaxDynamicSharedMemorySize,
                         FUSED_SMEM);

    fused_kernel<<<NCTA, 256, FUSED_SMEM>>>(qkv);
    gate_kernel<<<1, NWIN>>>();
    blend_kernel<<<(B_ * HW_ * C_ / 4) / 256, 256>>>(resx, out);
}

// round 5
// speedup vs baseline: 1.1145x; 1.1145x over previous
#include <cuda_runtime.h>
#include <math.h>
#include <cstdint>

// Problem constants
#define B_    4
#define H_    128
#define W_    128
#define C_    256
#define NH_   8
#define HD_   32
#define HW_   (H_ * W_)                 // 16384
#define NWIN  (B_ * H_)                 // 512
#define NCTA  (NWIN * NH_)              // 4096
#define QKV_STRIDE ((size_t)B_ * HW_ * C_)

// Scratch: ungated attention output y = (1-cos(...)) @ V  (67 MB fp32)
__device__ float g_y[(size_t)B_ * HW_ * C_];
__device__ float g_wsum[NWIN];
__device__ float g_M[NWIN];

// ---------------- packed f32x2 FMA helpers ----------------
#define FFMA2(d, a, b) \
    asm volatile("fma.rn.f32x2 %0, %1, %2, %0;" : "+l"(d) : "l"(a), "l"(b))
#define BCAST2(d, x) \
    asm volatile("mov.b64 %0, {%1, %1};" : "=l"(d) : "r"(__float_as_uint(x)))
#define UNPK2(lo, hi, v) \
    asm volatile("mov.b64 {%0, %1}, %2;" : "=r"(lo), "=r"(hi) : "l"(v))

// ---------------- tf32 mma.sync (sm_80+ baseline, works on sm_103) ----------
#define MMA_TF32(c0, c1, c2, c3, a0, a1, a2, a3, b0, b1) \
    asm volatile("mma.sync.aligned.m16n8k8.row.col.f32.tf32.tf32.f32 " \
        "{%0,%1,%2,%3}, {%4,%5,%6,%7}, {%8,%9}, {%0,%1,%2,%3};" \
        : "+f"(c0), "+f"(c1), "+f"(c2), "+f"(c3) \
        : "r"(a0), "r"(a1), "r"(a2), "r"(a3), "r"(b0), "r"(b1))

// ---------------- fused kernel smem layout (float offsets) ----------------
// Phase 1 (QK): Qt[128][36] @0, dQ @4608, Kt @9216, dK @13824  (end 18432)
// Phase 2 (AV): As[128][132] @0 (16896 floats, aliases staging)
// Always:       Vs[128][32] @18432, magt[256] @22528, wsum[8] @22784
#define QT_F       0
#define DQ_F       4608
#define KT_F       9216
#define DK_F       13824
#define AS_F       0
#define AS_STRIDE  132
#define VS_F       18432
#define MAGT_F     22528
#define WS_F       22784
#define SMEM_FLOATS 22792
#define FUSED_SMEM (SMEM_FLOATS * 4)   // 91,168 bytes

// ---------------------------------------------------------------------------
// Fused kernel, per (window, head):
//   1. stage split-tf32 Q/K (Qt,dQ,Kt,dK as [row][36]) + V into smem
//   2. QK^T on the tensor pipe: 3-term split-tf32 mma.sync (fp32 accuracy)
//      warp w owns output rows 16w..16w+15, all 128 cols
//   3. +RPE bias, |.| sums, per-row L2 norm (intra-warp), 1-cos -> As
//   4. As @ V via FFMA2 -> g_y (gate M deferred to blend kernel)
// ---------------------------------------------------------------------------
__global__ __launch_bounds__(256, 2) void fused_kernel(const float* __restrict__ qkv) {
    extern __shared__ float sm[];

    const int bx  = blockIdx.x;        // 0..4095
    const int wi  = bx >> 3;
    const int n   = bx & 7;
    const int b   = wi >> 7;
    const int h   = wi & 127;
    const int tid = threadIdx.x;
    const int wid = tid >> 5;
    const int lane = tid & 31;

    // RPE magnitude table: delta(q,k) = (k - q) * 2*pi/127
    if (tid < 255) {
        float delta = (float)(tid - 127) * (6.283185307179586477f / 127.0f);
        sm[MAGT_F + tid] = sqrtf(fmaxf(2.0f - 2.0f * cosf(delta), 0.0f));
    }

    // Stage split-tf32 Q/K + V
    const float* qb = qkv + ((size_t)(b * HW_) + (size_t)h * W_) * C_ + n * HD_;
    const float* kb = qb + QKV_STRIDE;
    const float* vb = kb + QKV_STRIDE;
    #pragma unroll
    for (int t = 0; t < 4; ++t) {
        int idx = tid + t * 256;       // 1024 float4 chunks
        int w   = idx >> 3;            // row 0..127
        int d4  = (idx & 7) << 2;      // 0,4,...,28
        float4 qv = *(const float4*)(qb + (size_t)w * C_ + d4);
        float4 kv = *(const float4*)(kb + (size_t)w * C_ + d4);
        float4 vv = *(const float4*)(vb + (size_t)w * C_ + d4);
        float4 qh, ql, kh, kl;
        qh.x = __uint_as_float(__float_as_uint(qv.x) & 0xFFFFE000u); ql.x = qv.x - qh.x;
        qh.y = __uint_as_float(__float_as_uint(qv.y) & 0xFFFFE000u); ql.y = qv.y - qh.y;
        qh.z = __uint_as_float(__float_as_uint(qv.z) & 0xFFFFE000u); ql.z = qv.z - qh.z;
        qh.w = __uint_as_float(__float_as_uint(qv.w) & 0xFFFFE000u); ql.w = qv.w - qh.w;
        kh.x = __uint_as_float(__float_as_uint(kv.x) & 0xFFFFE000u); kl.x = kv.x - kh.x;
        kh.y = __uint_as_float(__float_as_uint(kv.y) & 0xFFFFE000u); kl.y = kv.y - kh.y;
        kh.z = __uint_as_float(__float_as_uint(kv.z) & 0xFFFFE000u); kl.z = kv.z - kh.z;
        kh.w = __uint_as_float(__float_as_uint(kv.w) & 0xFFFFE000u); kl.w = kv.w - kh.w;
        int so = w * 36 + d4;
        *(float4*)(sm + QT_F + so) = qh;
        *(float4*)(sm + DQ_F + so) = ql;
        *(float4*)(sm + KT_F + so) = kh;
        *(float4*)(sm + DK_F + so) = kl;
        *(float4*)(sm + VS_F + w * 32 + d4) = vv;
    }
    __syncthreads();

    // ---- QK^T on tensor pipe: warp wid -> rows 16*wid..16*wid+15 ----
    float c[16][4];
    #pragma unroll
    for (int nt = 0; nt < 16; ++nt)
        #pragma unroll
        for (int j = 0; j < 4; ++j) c[nt][j] = 0.0f;

    const int arow = 16 * wid + (lane >> 2);
    #pragma unroll
    for (int ch = 0; ch < 4; ++ch) {
        const int ac = 8 * ch + (lane & 3);
        uint32_t qt0 = __float_as_uint(sm[QT_F + arow * 36 + ac]);
        uint32_t qt1 = __float_as_uint(sm[QT_F + (arow + 8) * 36 + ac]);
        uint32_t qt2 = __float_as_uint(sm[QT_F + arow * 36 + ac + 4]);
        uint32_t qt3 = __float_as_uint(sm[QT_F + (arow + 8) * 36 + ac + 4]);
        uint32_t dq0 = __float_as_uint(sm[DQ_F + arow * 36 + ac]);
        uint32_t dq1 = __float_as_uint(sm[DQ_F + (arow + 8) * 36 + ac]);
        uint32_t dq2 = __float_as_uint(sm[DQ_F + arow * 36 + ac + 4]);
        uint32_t dq3 = __float_as_uint(sm[DQ_F + (arow + 8) * 36 + ac + 4]);
        #pragma unroll
        for (int nt = 0; nt < 16; ++nt) {
            const int brow = 8 * nt + (lane >> 2);
            const int bc   = 8 * ch + (lane & 3);
            uint32_t kt0 = __float_as_uint(sm[KT_F + brow * 36 + bc]);
            uint32_t kt1 = __float_as_uint(sm[KT_F + brow * 36 + bc + 4]);
            uint32_t dk0 = __float_as_uint(sm[DK_F + brow * 36 + bc]);
            uint32_t dk1 = __float_as_uint(sm[DK_F + brow * 36 + bc + 4]);
            MMA_TF32(c[nt][0], c[nt][1], c[nt][2], c[nt][3],
                     qt0, qt1, qt2, qt3, kt0, kt1);
            MMA_TF32(c[nt][0], c[nt][1], c[nt][2], c[nt][3],
                     dq0, dq1, dq2, dq3, kt0, kt1);
            MMA_TF32(c[nt][0], c[nt][1], c[nt][2], c[nt][3],
                     qt0, qt1, qt2, qt3, dk0, dk1);
        }
    }

    // ---- epilogue: +bias, |.| sum, row sumsq (rows r1, r2 intra-warp) ----
    const int r1 = 16 * wid + (lane >> 2);
    const int r2 = r1 + 8;
    const float bscale = 0.1f * sinf((float)h * (3.14159265358979323846f / 128.0f));
    float sq1 = 0.0f, sq2 = 0.0f, s_abs = 0.0f;
    #pragma unroll
    for (int nt = 0; nt < 16; ++nt) {
        const int col0 = 8 * nt + 2 * (lane & 3);
        float v0 = c[nt][0] + ((col0     > r1) ? bscale : -bscale) * sm[MAGT_F + (col0     - r1 + 127)];
        float v1 = c[nt][1] + ((col0 + 1 > r1) ? bscale : -bscale) * sm[MAGT_F + (col0 + 1 - r1 + 127)];
        float v2 = c[nt][2] + ((col0     > r2) ? bscale : -bscale) * sm[MAGT_F + (col0     - r2 + 127)];
        float v3 = c[nt][3] + ((col0 + 1 > r2) ? bscale : -bscale) * sm[MAGT_F + (col0 + 1 - r2 + 127)];
        c[nt][0] = v0; c[nt][1] = v1; c[nt][2] = v2; c[nt][3] = v3;
        sq1 += v0 * v0 + v1 * v1;
        sq2 += v2 * v2 + v3 * v3;
        s_abs += fabsf(v0) + fabsf(v1) + fabsf(v2) + fabsf(v3);
    }
    // row sums across the 4 lanes sharing each row (lanes differ in bits 0-1)
    sq1 += __shfl_xor_sync(0xffffffffu, sq1, 1);
    sq1 += __shfl_xor_sync(0xffffffffu, sq1, 2);
    sq2 += __shfl_xor_sync(0xffffffffu, sq2, 1);
    sq2 += __shfl_xor_sync(0xffffffffu, sq2, 2);
    // per-window |attn| partial
    #pragma unroll
    for (int m = 16; m; m >>= 1)
        s_abs += __shfl_xor_sync(0xffffffffu, s_abs, m);
    if (lane == 0) sm[WS_F + wid] = s_abs;

    __syncthreads();   // staging reads done; WS_F visible; As may overwrite

    if (tid == 0) {
        float s = 0.0f;
        #pragma unroll
        for (int i = 0; i < 8; ++i) s += sm[WS_F + i];
        atomicAdd(&g_wsum[wi], s);
    }

    // ---- transform: 1 - cos(v * (pi/2)/norm)  (no gate M) -> As ----
    {
        const float inv1 = 1.57079632679489662f / fmaxf(sqrtf(sq1), 1e-12f);
        const float inv2 = 1.57079632679489662f / fmaxf(sqrtf(sq2), 1e-12f);
        #pragma unroll
        for (int nt = 0; nt < 16; ++nt) {
            const int col0 = 8 * nt + 2 * (lane & 3);
            float2 p1, p2;
            p1.x = 1.0f - __cosf(c[nt][0] * inv1);
            p1.y = 1.0f - __cosf(c[nt][1] * inv1);
            p2.x = 1.0f - __cosf(c[nt][2] * inv2);
            p2.y = 1.0f - __cosf(c[nt][3] * inv2);
            *(float2*)(sm + AS_F + r1 * AS_STRIDE + col0) = p1;
            *(float2*)(sm + AS_F + r2 * AS_STRIDE + col0) = p2;
        }
    }
    __syncthreads();

    // ---- AV GEMM: y[128 q][32 d] = As @ V, 4x4 thread tile, FFMA2 ----
    const int qg = (tid >> 3) << 2;   // 0..124
    const int dg = (tid & 7) << 2;    // 0..28
    unsigned long long oacc[4][2];
    #pragma unroll
    for (int i = 0; i < 4; ++i) { oacc[i][0] = 0ULL; oacc[i][1] = 0ULL; }

    #pragma unroll 4
    for (int kkb = 0; kkb < 128; kkb += 4) {
        __align__(16) float aa[4][4];
        #pragma unroll
        for (int i = 0; i < 4; ++i)
            *(float4*)(aa[i]) = *(const float4*)(sm + AS_F + (qg + i) * AS_STRIDE + kkb);
        #pragma unroll
        for (int t = 0; t < 4; ++t) {
            ulonglong2 bv = *(const ulonglong2*)(sm + VS_F + (kkb + t) * 32 + dg);
            #pragma unroll
            for (int i = 0; i < 4; ++i) {
                unsigned long long ad;
                BCAST2(ad, aa[i][t]);
                FFMA2(oacc[i][0], ad, bv.x);
                FFMA2(oacc[i][1], ad, bv.y);
            }
        }
    }

    const size_t obase = ((size_t)(b * HW_) + (size_t)h * W_) * C_ + n * HD_;
    #pragma unroll
    for (int i = 0; i < 4; ++i) {
        unsigned int lo, hi;
        __align__(16) float o[4];
        UNPK2(lo, hi, oacc[i][0]);
        o[0] = __uint_as_float(lo); o[1] = __uint_as_float(hi);
        UNPK2(lo, hi, oacc[i][1]);
        o[2] = __uint_as_float(lo); o[3] = __uint_as_float(hi);
        *(float4*)(g_y + obase + (size_t)(qg + i) * C_ + dg) = *(float4*)o;
    }
}

// ---------------------------------------------------------------------------
// Gate: mean |attn| per window, global max, M = max(mean/max, 0.5).
// Resets g_wsum for the next graph replay.
// ---------------------------------------------------------------------------
__global__ void gate_kernel() {
    __shared__ float red[512];
    const int t = threadIdx.x;
    float mean = g_wsum[t] * (1.0f / 131072.0f);   // / (NH*W*W)
    g_wsum[t] = 0.0f;
    red[t] = mean;
    __syncthreads();
    for (int s = 256; s > 0; s >>= 1) {
        if (t < s) red[t] = fmaxf(red[t], red[t + s]);
        __syncthreads();
    }
    g_M[t] = fmaxf(mean / red[0], 0.5f);
}

// ---------------------------------------------------------------------------
// Blend: out = M * y + (1 - M) * res   (pure bandwidth, float4)
// ---------------------------------------------------------------------------
__global__ __launch_bounds__(256) void blend_kernel(const float* __restrict__ resx,
                                                    float* __restrict__ out) {
    const int i  = blockIdx.x * 256 + threadIdx.x;   // float4 index
    const int wi = i >> 13;                          // / (W_*C_/4 = 8192)
    const float Mw   = g_M[wi];
    const float oneM = 1.0f - Mw;
    float4 y = ((const float4*)g_y)[i];
    float4 r = ((const float4*)resx)[i];
    float4 o;
    o.x = fmaf(Mw, y.x, oneM * r.x);
    o.y = fmaf(Mw, y.y, oneM * r.y);
    o.z = fmaf(Mw, y.z, oneM * r.z);
    o.w = fmaf(Mw, y.w, oneM * r.w);
    ((float4*)out)[i] = o;
}

// ---------------------------------------------------------------------------
extern "C" void kernel_launch(void* const* d_in, const int* in_sizes, int n_in,
                              void* d_out, int out_size) {
    (void)in_sizes; (void)n_in; (void)out_size;
    const float* qkv  = (const float*)d_in[0];
    const float* resx = (const float*)d_in[1];
    float* out = (float*)d_out;

    cudaFuncSetAttribute(fused_kernel, cudaFuncAttributeMaxDynamicSharedMemorySize,
                         FUSED_SMEM);

    fused_kernel<<<NCTA, 256, FUSED_SMEM>>>(qkv);
    gate_kernel<<<1, NWIN>>>();
    blend_kernel<<<(B_ * HW_ * C_ / 4) / 256, 256>>>(resx, out);
}

// round 6
// speedup vs baseline: 1.2673x; 1.1371x over previous
#include <cuda_runtime.h>
#include <math.h>
#include <cstdint>

// Problem constants
#define B_    4
#define H_    128
#define W_    128
#define C_    256
#define NH_   8
#define HD_   32
#define HW_   (H_ * W_)                 // 16384
#define NWIN  (B_ * H_)                 // 512
#define NCTA  (NWIN * NH_)              // 4096
#define QKV_STRIDE ((size_t)B_ * HW_ * C_)

// Scratch: ungated attention output y = (1-cos(...)) @ V  (67 MB fp32)
__device__ float g_y[(size_t)B_ * HW_ * C_];
__device__ float g_wsum[NWIN];
__device__ float g_M[NWIN];

// ---------------- tf32 mma.sync (sm_80+ baseline, works on sm_103) ----------
#define MMA_TF32(c0, c1, c2, c3, a0, a1, a2, a3, b0, b1) \
    asm volatile("mma.sync.aligned.m16n8k8.row.col.f32.tf32.tf32.f32 " \
        "{%0,%1,%2,%3}, {%4,%5,%6,%7}, {%8,%9}, {%0,%1,%2,%3};" \
        : "+f"(c0), "+f"(c1), "+f"(c2), "+f"(c3) \
        : "r"(a0), "r"(a1), "r"(a2), "r"(a3), "r"(b0), "r"(b1))

#define TF32_HI(x) __uint_as_float(__float_as_uint(x) & 0xFFFFE000u)

// ---------------- fused kernel smem layout (float offsets) ----------------
// Qt[128][36] @0, dQ @4608, Kt @9216, dK @13824
// Vs2[128][36] float2 {hi,lo} @18432 (9216 floats)
// magt[256] @27648, wsum[8] @27904
#define QT_F       0
#define DQ_F       4608
#define KT_F       9216
#define DK_F       13824
#define VS2_F      18432
#define MAGT_F     27648
#define WS_F       27904
#define SMEM_FLOATS 27912
#define FUSED_SMEM (SMEM_FLOATS * 4)   // 111,648 bytes

// ---------------------------------------------------------------------------
// Fused kernel, per (window, head):
//   1. stage split-tf32 Q/K ([row][36]) + split V ({hi,lo} float2) into smem
//   2. QK^T tensor pipe: 3-term split-tf32 mma; warp w owns rows 16w..16w+15
//   3. +RPE bias, |.| sums, per-row L2 norm (intra-warp), 1-cos  (registers)
//   4. AV on tensor pipe: A-frags from registers via quad shuffles (C->A
//      layout permutation), B-frags = split V from smem; 3-term split-tf32
//   5. store y (ungated; gate M applied in blend kernel)
// ---------------------------------------------------------------------------
__global__ __launch_bounds__(256, 2) void fused_kernel(const float* __restrict__ qkv) {
    extern __shared__ float sm[];

    const int bx  = blockIdx.x;        // 0..4095
    const int wi  = bx >> 3;
    const int n   = bx & 7;
    const int b   = wi >> 7;
    const int h   = wi & 127;
    const int tid = threadIdx.x;
    const int wid = tid >> 5;
    const int lane = tid & 31;

    // RPE magnitude table: delta(q,k) = (k - q) * 2*pi/127
    if (tid < 255) {
        float delta = (float)(tid - 127) * (6.283185307179586477f / 127.0f);
        sm[MAGT_F + tid] = sqrtf(fmaxf(2.0f - 2.0f * cosf(delta), 0.0f));
    }

    // Stage split-tf32 Q/K and split V
    const float* qb = qkv + ((size_t)(b * HW_) + (size_t)h * W_) * C_ + n * HD_;
    const float* kb = qb + QKV_STRIDE;
    const float* vb = kb + QKV_STRIDE;
    #pragma unroll
    for (int t = 0; t < 4; ++t) {
        int idx = tid + t * 256;       // 1024 float4 chunks
        int w   = idx >> 3;            // row 0..127
        int d4  = (idx & 7) << 2;      // 0,4,...,28
        float4 qv = *(const float4*)(qb + (size_t)w * C_ + d4);
        float4 kv = *(const float4*)(kb + (size_t)w * C_ + d4);
        float4 vv = *(const float4*)(vb + (size_t)w * C_ + d4);
        float4 qh, ql, kh, kl;
        qh.x = TF32_HI(qv.x); ql.x = qv.x - qh.x;
        qh.y = TF32_HI(qv.y); ql.y = qv.y - qh.y;
        qh.z = TF32_HI(qv.z); ql.z = qv.z - qh.z;
        qh.w = TF32_HI(qv.w); ql.w = qv.w - qh.w;
        kh.x = TF32_HI(kv.x); kl.x = kv.x - kh.x;
        kh.y = TF32_HI(kv.y); kl.y = kv.y - kh.y;
        kh.z = TF32_HI(kv.z); kl.z = kv.z - kh.z;
        kh.w = TF32_HI(kv.w); kl.w = kv.w - kh.w;
        int so = w * 36 + d4;
        *(float4*)(sm + QT_F + so) = qh;
        *(float4*)(sm + DQ_F + so) = ql;
        *(float4*)(sm + KT_F + so) = kh;
        *(float4*)(sm + DK_F + so) = kl;
        // V split, interleaved {hi,lo}: Vs2[k=w][n=d]
        float vf[4] = {vv.x, vv.y, vv.z, vv.w};
        #pragma unroll
        for (int d = 0; d < 4; ++d) {
            float vh = TF32_HI(vf[d]);
            float2 p; p.x = vh; p.y = vf[d] - vh;
            *(float2*)(sm + VS2_F + 2 * (w * 36 + d4 + d)) = p;
        }
    }
    __syncthreads();

    // ---- QK^T on tensor pipe: warp wid -> rows 16*wid..16*wid+15 ----
    float c[16][4];
    #pragma unroll
    for (int nt = 0; nt < 16; ++nt)
        #pragma unroll
        for (int j = 0; j < 4; ++j) c[nt][j] = 0.0f;

    const int arow = 16 * wid + (lane >> 2);
    #pragma unroll
    for (int ch = 0; ch < 4; ++ch) {
        const int ac = 8 * ch + (lane & 3);
        uint32_t qt0 = __float_as_uint(sm[QT_F + arow * 36 + ac]);
        uint32_t qt1 = __float_as_uint(sm[QT_F + (arow + 8) * 36 + ac]);
        uint32_t qt2 = __float_as_uint(sm[QT_F + arow * 36 + ac + 4]);
        uint32_t qt3 = __float_as_uint(sm[QT_F + (arow + 8) * 36 + ac + 4]);
        uint32_t dq0 = __float_as_uint(sm[DQ_F + arow * 36 + ac]);
        uint32_t dq1 = __float_as_uint(sm[DQ_F + (arow + 8) * 36 + ac]);
        uint32_t dq2 = __float_as_uint(sm[DQ_F + arow * 36 + ac + 4]);
        uint32_t dq3 = __float_as_uint(sm[DQ_F + (arow + 8) * 36 + ac + 4]);
        #pragma unroll
        for (int nt = 0; nt < 16; ++nt) {
            const int brow = 8 * nt + (lane >> 2);
            const int bc   = 8 * ch + (lane & 3);
            uint32_t kt0 = __float_as_uint(sm[KT_F + brow * 36 + bc]);
            uint32_t kt1 = __float_as_uint(sm[KT_F + brow * 36 + bc + 4]);
            uint32_t dk0 = __float_as_uint(sm[DK_F + brow * 36 + bc]);
            uint32_t dk1 = __float_as_uint(sm[DK_F + brow * 36 + bc + 4]);
            MMA_TF32(c[nt][0], c[nt][1], c[nt][2], c[nt][3],
                     qt0, qt1, qt2, qt3, kt0, kt1);
            MMA_TF32(c[nt][0], c[nt][1], c[nt][2], c[nt][3],
                     dq0, dq1, dq2, dq3, kt0, kt1);
            MMA_TF32(c[nt][0], c[nt][1], c[nt][2], c[nt][3],
                     qt0, qt1, qt2, qt3, dk0, dk1);
        }
    }

    // ---- epilogue: +bias, |.| sum, row sumsq (rows r1, r2 intra-warp) ----
    const int r1 = 16 * wid + (lane >> 2);
    const int r2 = r1 + 8;
    const float bscale = 0.1f * sinf((float)h * (3.14159265358979323846f / 128.0f));
    float sq1 = 0.0f, sq2 = 0.0f, s_abs = 0.0f;
    #pragma unroll
    for (int nt = 0; nt < 16; ++nt) {
        const int col0 = 8 * nt + 2 * (lane & 3);
        float v0 = c[nt][0] + ((col0     > r1) ? bscale : -bscale) * sm[MAGT_F + (col0     - r1 + 127)];
        float v1 = c[nt][1] + ((col0 + 1 > r1) ? bscale : -bscale) * sm[MAGT_F + (col0 + 1 - r1 + 127)];
        float v2 = c[nt][2] + ((col0     > r2) ? bscale : -bscale) * sm[MAGT_F + (col0     - r2 + 127)];
        float v3 = c[nt][3] + ((col0 + 1 > r2) ? bscale : -bscale) * sm[MAGT_F + (col0 + 1 - r2 + 127)];
        c[nt][0] = v0; c[nt][1] = v1; c[nt][2] = v2; c[nt][3] = v3;
        sq1 += v0 * v0 + v1 * v1;
        sq2 += v2 * v2 + v3 * v3;
        s_abs += fabsf(v0) + fabsf(v1) + fabsf(v2) + fabsf(v3);
    }
    sq1 += __shfl_xor_sync(0xffffffffu, sq1, 1);
    sq1 += __shfl_xor_sync(0xffffffffu, sq1, 2);
    sq2 += __shfl_xor_sync(0xffffffffu, sq2, 1);
    sq2 += __shfl_xor_sync(0xffffffffu, sq2, 2);
    #pragma unroll
    for (int m = 16; m; m >>= 1)
        s_abs += __shfl_xor_sync(0xffffffffu, s_abs, m);
    if (lane == 0) sm[WS_F + wid] = s_abs;

    // ---- transform in registers: c <- 1 - cos(v * (pi/2)/norm) ----
    {
        const float inv1 = 1.57079632679489662f / fmaxf(sqrtf(sq1), 1e-12f);
        const float inv2 = 1.57079632679489662f / fmaxf(sqrtf(sq2), 1e-12f);
        #pragma unroll
        for (int nt = 0; nt < 16; ++nt) {
            c[nt][0] = 1.0f - __cosf(c[nt][0] * inv1);
            c[nt][1] = 1.0f - __cosf(c[nt][1] * inv1);
            c[nt][2] = 1.0f - __cosf(c[nt][2] * inv2);
            c[nt][3] = 1.0f - __cosf(c[nt][3] * inv2);
        }
    }

    __syncthreads();   // WS_F visible for the window-sum reduction
    if (tid == 0) {
        float s = 0.0f;
        #pragma unroll
        for (int i = 0; i < 8; ++i) s += sm[WS_F + i];
        atomicAdd(&g_wsum[wi], s);
    }

    // ---- AV on tensor pipe: out[16 rows][32 d] per warp ----
    // A-frags from c[] via quad shuffles (C-layout cols {2j,2j+1} -> A-layout
    // cols {j, j+4}); B-frags = split V (hi,lo) from smem.
    float oacc[4][4];
    #pragma unroll
    for (int nt = 0; nt < 4; ++nt)
        #pragma unroll
        for (int j = 0; j < 4; ++j) oacc[nt][j] = 0.0f;

    const int jl   = lane & 3;
    const int s0   = (lane & ~3) | (jl >> 1);
    const int s1   = s0 + 2;
    const bool odd = (lane & 1);

    #pragma unroll
    for (int ch = 0; ch < 16; ++ch) {
        // gather A values: rows r1/r2, cols jl and jl+4 within k-block ch
        float e0 = __shfl_sync(0xffffffffu, c[ch][0], s0);
        float e1 = __shfl_sync(0xffffffffu, c[ch][1], s0);
        float f0 = __shfl_sync(0xffffffffu, c[ch][0], s1);
        float f1 = __shfl_sync(0xffffffffu, c[ch][1], s1);
        float g0 = __shfl_sync(0xffffffffu, c[ch][2], s0);
        float g1 = __shfl_sync(0xffffffffu, c[ch][3], s0);
        float h0 = __shfl_sync(0xffffffffu, c[ch][2], s1);
        float h1 = __shfl_sync(0xffffffffu, c[ch][3], s1);
        float a0 = odd ? e1 : e0;   // row r1, col jl
        float a2 = odd ? f1 : f0;   // row r1, col jl+4
        float a1 = odd ? g1 : g0;   // row r2, col jl
        float a3 = odd ? h1 : h0;   // row r2, col jl+4
        float a0h = TF32_HI(a0), a0l = a0 - a0h;
        float a1h = TF32_HI(a1), a1l = a1 - a1h;
        float a2h = TF32_HI(a2), a2l = a2 - a2h;
        float a3h = TF32_HI(a3), a3l = a3 - a3h;
        uint32_t A0h = __float_as_uint(a0h), A1h = __float_as_uint(a1h);
        uint32_t A2h = __float_as_uint(a2h), A3h = __float_as_uint(a3h);
        uint32_t A0l = __float_as_uint(a0l), A1l = __float_as_uint(a1l);
        uint32_t A2l = __float_as_uint(a2l), A3l = __float_as_uint(a3l);

        const int k0 = 8 * ch + jl;
        #pragma unroll
        for (int nt = 0; nt < 4; ++nt) {
            const int ncol = 8 * nt + (lane >> 2);
            float2 b0p = *(const float2*)(sm + VS2_F + 2 * (k0 * 36 + ncol));
            float2 b1p = *(const float2*)(sm + VS2_F + 2 * ((k0 + 4) * 36 + ncol));
            uint32_t Bh0 = __float_as_uint(b0p.x), Bl0 = __float_as_uint(b0p.y);
            uint32_t Bh1 = __float_as_uint(b1p.x), Bl1 = __float_as_uint(b1p.y);
            MMA_TF32(oacc[nt][0], oacc[nt][1], oacc[nt][2], oacc[nt][3],
                     A0h, A1h, A2h, A3h, Bh0, Bh1);
            MMA_TF32(oacc[nt][0], oacc[nt][1], oacc[nt][2], oacc[nt][3],
                     A0l, A1l, A2l, A3l, Bh0, Bh1);
            MMA_TF32(oacc[nt][0], oacc[nt][1], oacc[nt][2], oacc[nt][3],
                     A0h, A1h, A2h, A3h, Bl0, Bl1);
        }
    }

    // ---- store y (ungated): C-layout float2 pairs ----
    const size_t obase = ((size_t)(b * HW_) + (size_t)h * W_) * C_ + n * HD_;
    const int ocol = 2 * jl;
    #pragma unroll
    for (int nt = 0; nt < 4; ++nt) {
        float2 p1; p1.x = oacc[nt][0]; p1.y = oacc[nt][1];
        float2 p2; p2.x = oacc[nt][2]; p2.y = oacc[nt][3];
        *(float2*)(g_y + obase + (size_t)r1 * C_ + 8 * nt + ocol) = p1;
        *(float2*)(g_y + obase + (size_t)r2 * C_ + 8 * nt + ocol) = p2;
    }
}

// ---------------------------------------------------------------------------
// Gate: mean |attn| per window, global max, M = max(mean/max, 0.5).
// Resets g_wsum for the next graph replay.
// ---------------------------------------------------------------------------
__global__ void gate_kernel() {
    __shared__ float red[512];
    const int t = threadIdx.x;
    float mean = g_wsum[t] * (1.0f / 131072.0f);   // / (NH*W*W)
    g_wsum[t] = 0.0f;
    red[t] = mean;
    __syncthreads();
    for (int s = 256; s > 0; s >>= 1) {
        if (t < s) red[t] = fmaxf(red[t], red[t + s]);
        __syncthreads();
    }
    g_M[t] = fmaxf(mean / red[0], 0.5f);
}

// ---------------------------------------------------------------------------
// Blend: out = M * y + (1 - M) * res   (pure bandwidth, float4)
// ---------------------------------------------------------------------------
__global__ __launch_bounds__(256) void blend_kernel(const float* __restrict__ resx,
                                                    float* __restrict__ out) {
    const int i  = blockIdx.x * 256 + threadIdx.x;   // float4 index
    const int wi = i >> 13;                          // / (W_*C_/4 = 8192)
    const float Mw   = g_M[wi];
    const float oneM = 1.0f - Mw;
    float4 y = ((const float4*)g_y)[i];
    float4 r = ((const float4*)resx)[i];
    float4 o;
    o.x = fmaf(Mw, y.x, oneM * r.x);
    o.y = fmaf(Mw, y.y, oneM * r.y);
    o.z = fmaf(Mw, y.z, oneM * r.z);
    o.w = fmaf(Mw, y.w, oneM * r.w);
    ((float4*)out)[i] = o;
}

// ---------------------------------------------------------------------------
extern "C" void kernel_launch(void* const* d_in, const int* in_sizes, int n_in,
                              void* d_out, int out_size) {
    (void)in_sizes; (void)n_in; (void)out_size;
    const float* qkv  = (const float*)d_in[0];
    const float* resx = (const float*)d_in[1];
    float* out = (float*)d_out;

    cudaFuncSetAttribute(fused_kernel, cudaFuncAttributeMaxDynamicSharedMemorySize,
                         FUSED_SMEM);

    fused_kernel<<<NCTA, 256, FUSED_SMEM>>>(qkv);
    gate_kernel<<<1, NWIN>>>();
    blend_kernel<<<(B_ * HW_ * C_ / 4) / 256, 256>>>(resx, out);
}

// round 7
// speedup vs baseline: 1.2958x; 1.0225x over previous
#include <cuda_runtime.h>
#include <cuda_bf16.h>
#include <math.h>
#include <cstdint>

// Problem constants
#define B_    4
#define H_    128
#define W_    128
#define C_    256
#define NH_   8
#define HD_   32
#define HW_   (H_ * W_)                 // 16384
#define NWIN  (B_ * H_)                 // 512
#define NCTA  (NWIN * NH_)              // 4096
#define QKV_STRIDE ((size_t)B_ * HW_ * C_)

// Scratch: ungated attention output y = (1-cos(...)) @ V  (67 MB fp32)
__device__ float g_y[(size_t)B_ * HW_ * C_];
__device__ float g_wsum[NWIN];
__device__ float g_M[NWIN];

// ---------------- bf16 m16n8k16 mma.sync (sm_80+ baseline) ----------------
#define MMA_BF16(c0, c1, c2, c3, a0, a1, a2, a3, b0, b1) \
    asm volatile("mma.sync.aligned.m16n8k16.row.col.f32.bf16.bf16.f32 " \
        "{%0,%1,%2,%3}, {%4,%5,%6,%7}, {%8,%9}, {%0,%1,%2,%3};" \
        : "+f"(c0), "+f"(c1), "+f"(c2), "+f"(c3) \
        : "r"(a0), "r"(a1), "r"(a2), "r"(a3), "r"(b0), "r"(b1))

// Split-pack: x -> {bf16 hi-plane, bf16 residual-plane}, two values per u32
__device__ __forceinline__ void split_pack(float lo, float hi,
                                           uint32_t& hp, uint32_t& lp) {
    __nv_bfloat162 h2 = __floats2bfloat162_rn(lo, hi);    // low = lo
    float rl = lo - __bfloat162float(h2.x);
    float rh = hi - __bfloat162float(h2.y);
    __nv_bfloat162 l2 = __floats2bfloat162_rn(rl, rh);
    hp = *(uint32_t*)&h2;
    lp = *(uint32_t*)&l2;
}

// ---------------- fused kernel smem layout (u32 word offsets) --------------
// QHP/QLP/KHP/KLP: [128 rows][20 stride] bf16x2 d-pairs (16 used)
// VHP/VLP:         [32 d-rows][68 stride] bf16x2 k-pairs (64 used)
#define QHP_U      0
#define QLP_U      2560
#define KHP_U      5120
#define KLP_U      7680
#define VHP_U      10240
#define VLP_U      12416
#define MAGT_U     14592
#define WS_U       14848
#define SMEM_WORDS 14856
#define FUSED_SMEM (SMEM_WORDS * 4)    // 59,424 bytes

// ---------------------------------------------------------------------------
// Fused kernel, per (window, head):
//   1. stage split-bf16 Q/K (d-paired) and V (k-paired, transposed) in smem
//   2. QK^T: 3-term split-bf16 m16n8k16; warp w owns rows 16w..16w+15
//   3. +RPE bias, |.| sums, per-row L2 norm (intra-warp), 1-cos (registers)
//   4. AV: A-frags are direct repacks of the C tiles (k16 pairing == C
//      column pairing, same warp) -- no shuffles; B-frags = split V
//   5. store ungated y (gate M applied in blend kernel)
// ---------------------------------------------------------------------------
__global__ __launch_bounds__(256, 2) void fused_kernel(const float* __restrict__ qkv) {
    extern __shared__ uint32_t smu[];
    float* smf = (float*)smu;

    const int bx  = blockIdx.x;        // 0..4095
    const int wi  = bx >> 3;
    const int n   = bx & 7;
    const int b   = wi >> 7;
    const int h   = wi & 127;
    const int tid = threadIdx.x;
    const int wid = tid >> 5;
    const int lane = tid & 31;

    // RPE magnitude table: delta(q,k) = (k - q) * 2*pi/127
    if (tid < 255) {
        float delta = (float)(tid - 127) * (6.283185307179586477f / 127.0f);
        smf[MAGT_U + tid] = sqrtf(fmaxf(2.0f - 2.0f * cosf(delta), 0.0f));
    }

    const float* qb = qkv + ((size_t)(b * HW_) + (size_t)h * W_) * C_ + n * HD_;
    const float* kb = qb + QKV_STRIDE;
    const float* vb = kb + QKV_STRIDE;

    // Stage Q/K: split-bf16, packed d-pairs, row stride 20
    #pragma unroll
    for (int t = 0; t < 4; ++t) {
        int idx = tid + t * 256;       // 1024 float4 chunks
        int w   = idx >> 3;            // row 0..127
        int d4  = (idx & 7) << 2;      // 0,4,...,28
        float4 qv = *(const float4*)(qb + (size_t)w * C_ + d4);
        float4 kv = *(const float4*)(kb + (size_t)w * C_ + d4);
        uint32_t h0, l0, h1, l1;
        int base = w * 20 + (d4 >> 1);
        split_pack(qv.x, qv.y, h0, l0);
        split_pack(qv.z, qv.w, h1, l1);
        smu[QHP_U + base]     = h0;  smu[QHP_U + base + 1] = h1;
        smu[QLP_U + base]     = l0;  smu[QLP_U + base + 1] = l1;
        split_pack(kv.x, kv.y, h0, l0);
        split_pack(kv.z, kv.w, h1, l1);
        smu[KHP_U + base]     = h0;  smu[KHP_U + base + 1] = h1;
        smu[KLP_U + base]     = l0;  smu[KLP_U + base + 1] = l1;
    }
    // Stage V transposed: VHP[d][k-pair], k-pairs along tokens
    #pragma unroll
    for (int t = 0; t < 8; ++t) {
        int idx = tid + t * 256;       // 2048 items
        int d   = idx & 31;
        int w2  = idx >> 5;            // 0..63
        float v0 = vb[(size_t)(2 * w2)     * C_ + d];
        float v1 = vb[(size_t)(2 * w2 + 1) * C_ + d];
        uint32_t hp, lp;
        split_pack(v0, v1, hp, lp);
        smu[VHP_U + d * 68 + w2] = hp;
        smu[VLP_U + d * 68 + w2] = lp;
    }
    __syncthreads();

    // ---- QK^T: warp wid -> rows 16*wid..16*wid+15, 2 chunks of k16 ----
    float c[16][4];
    #pragma unroll
    for (int nt = 0; nt < 16; ++nt)
        #pragma unroll
        for (int j = 0; j < 4; ++j) c[nt][j] = 0.0f;

    const int arow = 16 * wid + (lane >> 2);
    const int jl   = lane & 3;
    #pragma unroll
    for (int ch = 0; ch < 2; ++ch) {
        const int pb = 8 * ch + jl;    // d-pair index
        uint32_t qh0 = smu[QHP_U + arow * 20 + pb];
        uint32_t qh1 = smu[QHP_U + (arow + 8) * 20 + pb];
        uint32_t qh2 = smu[QHP_U + arow * 20 + pb + 4];
        uint32_t qh3 = smu[QHP_U + (arow + 8) * 20 + pb + 4];
        uint32_t ql0 = smu[QLP_U + arow * 20 + pb];
        uint32_t ql1 = smu[QLP_U + (arow + 8) * 20 + pb];
        uint32_t ql2 = smu[QLP_U + arow * 20 + pb + 4];
        uint32_t ql3 = smu[QLP_U + (arow + 8) * 20 + pb + 4];
        #pragma unroll
        for (int nt = 0; nt < 16; ++nt) {
            const int krow = 8 * nt + (lane >> 2);
            uint32_t kh0 = smu[KHP_U + krow * 20 + pb];
            uint32_t kh1 = smu[KHP_U + krow * 20 + pb + 4];
            uint32_t kl0 = smu[KLP_U + krow * 20 + pb];
            uint32_t kl1 = smu[KLP_U + krow * 20 + pb + 4];
            MMA_BF16(c[nt][0], c[nt][1], c[nt][2], c[nt][3],
                     qh0, qh1, qh2, qh3, kh0, kh1);
            MMA_BF16(c[nt][0], c[nt][1], c[nt][2], c[nt][3],
                     ql0, ql1, ql2, ql3, kh0, kh1);
            MMA_BF16(c[nt][0], c[nt][1], c[nt][2], c[nt][3],
                     qh0, qh1, qh2, qh3, kl0, kl1);
        }
    }

    // ---- epilogue: +bias, |.| sum, row sumsq (rows r1, r2 intra-warp) ----
    const int r1 = arow;
    const int r2 = arow + 8;
    const float bscale = 0.1f * sinf((float)h * (3.14159265358979323846f / 128.0f));
    float sq1 = 0.0f, sq2 = 0.0f, s_abs = 0.0f;
    #pragma unroll
    for (int nt = 0; nt < 16; ++nt) {
        const int col0 = 8 * nt + 2 * jl;
        float v0 = c[nt][0] + ((col0     > r1) ? bscale : -bscale) * smf[MAGT_U + (col0     - r1 + 127)];
        float v1 = c[nt][1] + ((col0 + 1 > r1) ? bscale : -bscale) * smf[MAGT_U + (col0 + 1 - r1 + 127)];
        float v2 = c[nt][2] + ((col0     > r2) ? bscale : -bscale) * smf[MAGT_U + (col0     - r2 + 127)];
        float v3 = c[nt][3] + ((col0 + 1 > r2) ? bscale : -bscale) * smf[MAGT_U + (col0 + 1 - r2 + 127)];
        c[nt][0] = v0; c[nt][1] = v1; c[nt][2] = v2; c[nt][3] = v3;
        sq1 += v0 * v0 + v1 * v1;
        sq2 += v2 * v2 + v3 * v3;
        s_abs += fabsf(v0) + fabsf(v1) + fabsf(v2) + fabsf(v3);
    }
    sq1 += __shfl_xor_sync(0xffffffffu, sq1, 1);
    sq1 += __shfl_xor_sync(0xffffffffu, sq1, 2);
    sq2 += __shfl_xor_sync(0xffffffffu, sq2, 1);
    sq2 += __shfl_xor_sync(0xffffffffu, sq2, 2);
    #pragma unroll
    for (int m = 16; m; m >>= 1)
        s_abs += __shfl_xor_sync(0xffffffffu, s_abs, m);
    if (lane == 0) smf[WS_U + wid] = s_abs;

    // ---- transform in registers: c <- 1 - cos(v * (pi/2)/norm) ----
    {
        const float inv1 = 1.57079632679489662f / fmaxf(sqrtf(sq1), 1e-12f);
        const float inv2 = 1.57079632679489662f / fmaxf(sqrtf(sq2), 1e-12f);
        #pragma unroll
        for (int nt = 0; nt < 16; ++nt) {
            c[nt][0] = 1.0f - __cosf(c[nt][0] * inv1);
            c[nt][1] = 1.0f - __cosf(c[nt][1] * inv1);
            c[nt][2] = 1.0f - __cosf(c[nt][2] * inv2);
            c[nt][3] = 1.0f - __cosf(c[nt][3] * inv2);
        }
    }

    __syncthreads();   // WS visible
    if (tid == 0) {
        float s = 0.0f;
        #pragma unroll
        for (int i = 0; i < 8; ++i) s += smf[WS_U + i];
        atomicAdd(&g_wsum[wi], s);
    }

    // ---- AV: A-frags = direct repack of C tiles (no shuffles) ----
    float oacc[4][4];
    #pragma unroll
    for (int nt = 0; nt < 4; ++nt)
        #pragma unroll
        for (int j = 0; j < 4; ++j) oacc[nt][j] = 0.0f;

    #pragma unroll
    for (int ch = 0; ch < 8; ++ch) {
        // a0=(r1,k), a1=(r2,k), a2=(r1,k+8), a3=(r2,k+8)
        uint32_t ah0, al0, ah1, al1, ah2, al2, ah3, al3;
        split_pack(c[2 * ch][0],     c[2 * ch][1],     ah0, al0);
        split_pack(c[2 * ch][2],     c[2 * ch][3],     ah1, al1);
        split_pack(c[2 * ch + 1][0], c[2 * ch + 1][1], ah2, al2);
        split_pack(c[2 * ch + 1][2], c[2 * ch + 1][3], ah3, al3);
        const int kp = 8 * ch + jl;    // k-pair index
        #pragma unroll
        for (int nt = 0; nt < 4; ++nt) {
            const int nc = 8 * nt + (lane >> 2);   // d column
            uint32_t vh0 = smu[VHP_U + nc * 68 + kp];
            uint32_t vh1 = smu[VHP_U + nc * 68 + kp + 4];
            uint32_t vl0 = smu[VLP_U + nc * 68 + kp];
            uint32_t vl1 = smu[VLP_U + nc * 68 + kp + 4];
            MMA_BF16(oacc[nt][0], oacc[nt][1], oacc[nt][2], oacc[nt][3],
                     ah0, ah1, ah2, ah3, vh0, vh1);
            MMA_BF16(oacc[nt][0], oacc[nt][1], oacc[nt][2], oacc[nt][3],
                     al0, al1, al2, al3, vh0, vh1);
            MMA_BF16(oacc[nt][0], oacc[nt][1], oacc[nt][2], oacc[nt][3],
                     ah0, ah1, ah2, ah3, vl0, vl1);
        }
    }

    // ---- store y (ungated): C-layout float2 pairs ----
    const size_t obase = ((size_t)(b * HW_) + (size_t)h * W_) * C_ + n * HD_;
    const int ocol = 2 * jl;
    #pragma unroll
    for (int nt = 0; nt < 4; ++nt) {
        float2 p1; p1.x = oacc[nt][0]; p1.y = oacc[nt][1];
        float2 p2; p2.x = oacc[nt][2]; p2.y = oacc[nt][3];
        *(float2*)(g_y + obase + (size_t)r1 * C_ + 8 * nt + ocol) = p1;
        *(float2*)(g_y + obase + (size_t)r2 * C_ + 8 * nt + ocol) = p2;
    }
}

// ---------------------------------------------------------------------------
// Gate: mean |attn| per window, global max, M = max(mean/max, 0.5).
// Resets g_wsum for the next graph replay.
// ---------------------------------------------------------------------------
__global__ void gate_kernel() {
    __shared__ float red[512];
    const int t = threadIdx.x;
    float mean = g_wsum[t] * (1.0f / 131072.0f);   // / (NH*W*W)
    g_wsum[t] = 0.0f;
    red[t] = mean;
    __syncthreads();
    for (int s = 256; s > 0; s >>= 1) {
        if (t < s) red[t] = fmaxf(red[t], red[t + s]);
        __syncthreads();
    }
    g_M[t] = fmaxf(mean / red[0], 0.5f);
}

// ---------------------------------------------------------------------------
// Blend: out = M * y + (1 - M) * res   (pure bandwidth, float4)
// ---------------------------------------------------------------------------
__global__ __launch_bounds__(256) void blend_kernel(const float* __restrict__ resx,
                                                    float* __restrict__ out) {
    const int i  = blockIdx.x * 256 + threadIdx.x;   // float4 index
    const int wi = i >> 13;                          // / (W_*C_/4 = 8192)
    const float Mw   = g_M[wi];
    const float oneM = 1.0f - Mw;
    float4 y = ((const float4*)g_y)[i];
    float4 r = ((const float4*)resx)[i];
    float4 o;
    o.x = fmaf(Mw, y.x, oneM * r.x);
    o.y = fmaf(Mw, y.y, oneM * r.y);
    o.z = fmaf(Mw, y.z, oneM * r.z);
    o.w = fmaf(Mw, y.w, oneM * r.w);
    ((float4*)out)[i] = o;
}

// ---------------------------------------------------------------------------
extern "C" void kernel_launch(void* const* d_in, const int* in_sizes, int n_in,
                              void* d_out, int out_size) {
    (void)in_sizes; (void)n_in; (void)out_size;
    const float* qkv  = (const float*)d_in[0];
    const float* resx = (const float*)d_in[1];
    float* out = (float*)d_out;

    cudaFuncSetAttribute(fused_kernel, cudaFuncAttributeMaxDynamicSharedMemorySize,
                         FUSED_SMEM);

    fused_kernel<<<NCTA, 256, FUSED_SMEM>>>(qkv);
    gate_kernel<<<1, NWIN>>>();
    blend_kernel<<<(B_ * HW_ * C_ / 4) / 256, 256>>>(resx, out);
}

// round 8
// speedup vs baseline: 2.1051x; 1.6246x over previous
#include <cuda_runtime.h>
#include <cuda_fp16.h>
#include <math.h>
#include <cstdint>

// Problem constants
#define B_    4
#define H_    128
#define W_    128
#define C_    256
#define NH_   8
#define HD_   32
#define HW_   (H_ * W_)                 // 16384
#define NWIN  (B_ * H_)                 // 512
#define NCTA  (NWIN * NH_)              // 4096
#define QKV_STRIDE ((size_t)B_ * HW_ * C_)

// Scratch: ungated attention output y = (1-cos(...)) @ V  (67 MB fp32)
__device__ float g_y[(size_t)B_ * HW_ * C_];
__device__ float g_wsum[NWIN];
__device__ float g_M[NWIN];

// ---------------- fp16 m16n8k16 mma.sync (sm_80+ baseline) ----------------
#define MMA_F16(c0, c1, c2, c3, a0, a1, a2, a3, b0, b1) \
    asm volatile("mma.sync.aligned.m16n8k16.row.col.f32.f16.f16.f32 " \
        "{%0,%1,%2,%3}, {%4,%5,%6,%7}, {%8,%9}, {%0,%1,%2,%3};" \
        : "+f"(c0), "+f"(c1), "+f"(c2), "+f"(c3) \
        : "r"(a0), "r"(a1), "r"(a2), "r"(a3), "r"(b0), "r"(b1))

__device__ __forceinline__ uint32_t h2u(__half2 h) { return *(uint32_t*)&h; }

// ---------------- fused kernel smem layout (u32 word offsets) --------------
// QHP/QLP: [128 rows][20 stride] fp16x2 d-pairs (Q hi + residual planes)
// KHP:     [128 rows][20 stride] fp16x2 d-pairs (single plane)
// VHP:     [32 d-rows][68 stride] fp16x2 k-pairs (single plane, transposed)
// SCT:     float2[128] {sin(k*pi/127), cos(k*pi/127)}
#define QHP_U      0
#define QLP_U      2560
#define KHP_U      5120
#define VHP_U      7680
#define SCT_U      9856
#define WS_U       10112
#define SMEM_WORDS 10120
#define FUSED_SMEM (SMEM_WORDS * 4)    // 40,480 bytes

#define A127 (3.14159265358979323846f / 127.0f)

// ---------------------------------------------------------------------------
// Fused kernel, per (window, head):
//   1. stage Q (2-plane fp16), K (1-plane), V (1-plane, transposed) in smem
//   2. QK^T: (Qh+Ql)*Kh -> 2 mmas per k16; warp w owns rows 16w..16w+15
//   3. bias via exact identity 2*sin((k-q)pi/127) (sincos table, no gather),
//      |.| sums, per-row L2 norm (intra-warp), 1-cos in registers
//   4. AV: A 2-plane fp16 (direct C-tile repack), V 1-plane -> 2 mmas per k16
//   5. store ungated y (gate M applied in blend kernel)
// ---------------------------------------------------------------------------
__global__ __launch_bounds__(256, 2) void fused_kernel(const float* __restrict__ qkv) {
    extern __shared__ uint32_t smu[];
    float* smf = (float*)smu;

    const int bx  = blockIdx.x;        // 0..4095
    const int wi  = bx >> 3;
    const int n   = bx & 7;
    const int b   = wi >> 7;
    const int h   = wi & 127;
    const int tid = threadIdx.x;
    const int wid = tid >> 5;
    const int lane = tid & 31;

    // sincos table for the RPE bias identity
    if (tid < 128) {
        float a = (float)tid * A127;
        smf[SCT_U + 2 * tid]     = sinf(a);
        smf[SCT_U + 2 * tid + 1] = cosf(a);
    }

    const float* qb = qkv + ((size_t)(b * HW_) + (size_t)h * W_) * C_ + n * HD_;
    const float* kb = qb + QKV_STRIDE;
    const float* vb = kb + QKV_STRIDE;

    // Stage Q (split fp16) and K (single fp16): packed d-pairs, row stride 20
    #pragma unroll
    for (int t = 0; t < 4; ++t) {
        int idx = tid + t * 256;       // 1024 float4 chunks
        int w   = idx >> 3;            // row 0..127
        int d4  = (idx & 7) << 2;      // 0,4,...,28
        float4 qv = *(const float4*)(qb + (size_t)w * C_ + d4);
        float4 kv = *(const float4*)(kb + (size_t)w * C_ + d4);
        int base = w * 20 + (d4 >> 1);
        __half2 qh0 = __floats2half2_rn(qv.x, qv.y);
        __half2 qh1 = __floats2half2_rn(qv.z, qv.w);
        float2 qb0 = __half22float2(qh0);
        float2 qb1 = __half22float2(qh1);
        __half2 ql0 = __floats2half2_rn(qv.x - qb0.x, qv.y - qb0.y);
        __half2 ql1 = __floats2half2_rn(qv.z - qb1.x, qv.w - qb1.y);
        smu[QHP_U + base] = h2u(qh0);  smu[QHP_U + base + 1] = h2u(qh1);
        smu[QLP_U + base] = h2u(ql0);  smu[QLP_U + base + 1] = h2u(ql1);
        smu[KHP_U + base]     = h2u(__floats2half2_rn(kv.x, kv.y));
        smu[KHP_U + base + 1] = h2u(__floats2half2_rn(kv.z, kv.w));
    }
    // Stage V transposed (single fp16): VHP[d][k-pair]
    #pragma unroll
    for (int t = 0; t < 8; ++t) {
        int idx = tid + t * 256;       // 2048 items
        int d   = idx & 31;
        int w2  = idx >> 5;            // 0..63
        float v0 = vb[(size_t)(2 * w2)     * C_ + d];
        float v1 = vb[(size_t)(2 * w2 + 1) * C_ + d];
        smu[VHP_U + d * 68 + w2] = h2u(__floats2half2_rn(v0, v1));
    }
    __syncthreads();

    // ---- QK^T: warp wid -> rows 16*wid..16*wid+15, 2 chunks of k16 ----
    float c[16][4];
    #pragma unroll
    for (int nt = 0; nt < 16; ++nt)
        #pragma unroll
        for (int j = 0; j < 4; ++j) c[nt][j] = 0.0f;

    const int arow = 16 * wid + (lane >> 2);
    const int jl   = lane & 3;
    #pragma unroll
    for (int ch = 0; ch < 2; ++ch) {
        const int pb = 8 * ch + jl;    // d-pair index
        uint32_t qh0 = smu[QHP_U + arow * 20 + pb];
        uint32_t qh1 = smu[QHP_U + (arow + 8) * 20 + pb];
        uint32_t qh2 = smu[QHP_U + arow * 20 + pb + 4];
        uint32_t qh3 = smu[QHP_U + (arow + 8) * 20 + pb + 4];
        uint32_t ql0 = smu[QLP_U + arow * 20 + pb];
        uint32_t ql1 = smu[QLP_U + (arow + 8) * 20 + pb];
        uint32_t ql2 = smu[QLP_U + arow * 20 + pb + 4];
        uint32_t ql3 = smu[QLP_U + (arow + 8) * 20 + pb + 4];
        #pragma unroll
        for (int nt = 0; nt < 16; ++nt) {
            const int krow = 8 * nt + (lane >> 2);
            uint32_t kh0 = smu[KHP_U + krow * 20 + pb];
            uint32_t kh1 = smu[KHP_U + krow * 20 + pb + 4];
            MMA_F16(c[nt][0], c[nt][1], c[nt][2], c[nt][3],
                    qh0, qh1, qh2, qh3, kh0, kh1);
            MMA_F16(c[nt][0], c[nt][1], c[nt][2], c[nt][3],
                    ql0, ql1, ql2, ql3, kh0, kh1);
        }
    }

    // ---- epilogue: bias = bs2*sin((k-q)*pi/127) via sincos identity ----
    const int r1 = arow;
    const int r2 = arow + 8;
    const float bs2 = 0.2f * sinf((float)h * (3.14159265358979323846f / 128.0f));
    const float f1c = bs2 * cosf((float)r1 * A127);
    const float f1s = bs2 * sinf((float)r1 * A127);
    const float f2c = bs2 * cosf((float)r2 * A127);
    const float f2s = bs2 * sinf((float)r2 * A127);

    float sq1 = 0.0f, sq2 = 0.0f, s_abs = 0.0f;
    #pragma unroll
    for (int nt = 0; nt < 16; ++nt) {
        const int col0 = 8 * nt + 2 * jl;
        // {sin c0, cos c0, sin c1, cos c1}
        float4 t = *(const float4*)(smf + SCT_U + 2 * col0);
        float v0 = c[nt][0] + (t.x * f1c - t.y * f1s);
        float v1 = c[nt][1] + (t.z * f1c - t.w * f1s);
        float v2 = c[nt][2] + (t.x * f2c - t.y * f2s);
        float v3 = c[nt][3] + (t.z * f2c - t.w * f2s);
        c[nt][0] = v0; c[nt][1] = v1; c[nt][2] = v2; c[nt][3] = v3;
        sq1 += v0 * v0 + v1 * v1;
        sq2 += v2 * v2 + v3 * v3;
        s_abs += fabsf(v0) + fabsf(v1) + fabsf(v2) + fabsf(v3);
    }
    sq1 += __shfl_xor_sync(0xffffffffu, sq1, 1);
    sq1 += __shfl_xor_sync(0xffffffffu, sq1, 2);
    sq2 += __shfl_xor_sync(0xffffffffu, sq2, 1);
    sq2 += __shfl_xor_sync(0xffffffffu, sq2, 2);
    #pragma unroll
    for (int m = 16; m; m >>= 1)
        s_abs += __shfl_xor_sync(0xffffffffu, s_abs, m);
    if (lane == 0) smf[WS_U + wid] = s_abs;

    // ---- transform in registers: c <- 1 - cos(v * (pi/2)/norm) ----
    {
        const float inv1 = 1.57079632679489662f / fmaxf(sqrtf(sq1), 1e-12f);
        const float inv2 = 1.57079632679489662f / fmaxf(sqrtf(sq2), 1e-12f);
        #pragma unroll
        for (int nt = 0; nt < 16; ++nt) {
            c[nt][0] = 1.0f - __cosf(c[nt][0] * inv1);
            c[nt][1] = 1.0f - __cosf(c[nt][1] * inv1);
            c[nt][2] = 1.0f - __cosf(c[nt][2] * inv2);
            c[nt][3] = 1.0f - __cosf(c[nt][3] * inv2);
        }
    }

    __syncthreads();   // WS visible
    if (tid == 0) {
        float s = 0.0f;
        #pragma unroll
        for (int i = 0; i < 8; ++i) s += smf[WS_U + i];
        atomicAdd(&g_wsum[wi], s);
    }

    // ---- AV: A = 2-plane fp16 repack of C tiles (no shuffles), V 1-plane ----
    float oacc[4][4];
    #pragma unroll
    for (int nt = 0; nt < 4; ++nt)
        #pragma unroll
        for (int j = 0; j < 4; ++j) oacc[nt][j] = 0.0f;

    #pragma unroll
    for (int ch = 0; ch < 8; ++ch) {
        __half2 ha0 = __floats2half2_rn(c[2 * ch][0],     c[2 * ch][1]);
        __half2 ha1 = __floats2half2_rn(c[2 * ch][2],     c[2 * ch][3]);
        __half2 ha2 = __floats2half2_rn(c[2 * ch + 1][0], c[2 * ch + 1][1]);
        __half2 ha3 = __floats2half2_rn(c[2 * ch + 1][2], c[2 * ch + 1][3]);
        float2 b0 = __half22float2(ha0);
        float2 b1 = __half22float2(ha1);
        float2 b2 = __half22float2(ha2);
        float2 b3 = __half22float2(ha3);
        __half2 la0 = __floats2half2_rn(c[2 * ch][0] - b0.x,     c[2 * ch][1] - b0.y);
        __half2 la1 = __floats2half2_rn(c[2 * ch][2] - b1.x,     c[2 * ch][3] - b1.y);
        __half2 la2 = __floats2half2_rn(c[2 * ch + 1][0] - b2.x, c[2 * ch + 1][1] - b2.y);
        __half2 la3 = __floats2half2_rn(c[2 * ch + 1][2] - b3.x, c[2 * ch + 1][3] - b3.y);
        uint32_t ah0 = h2u(ha0), ah1 = h2u(ha1), ah2 = h2u(ha2), ah3 = h2u(ha3);
        uint32_t al0 = h2u(la0), al1 = h2u(la1), al2 = h2u(la2), al3 = h2u(la3);
        const int kp = 8 * ch + jl;    // k-pair index
        #pragma unroll
        for (int nt = 0; nt < 4; ++nt) {
            const int nc = 8 * nt + (lane >> 2);   // d column
            uint32_t vh0 = smu[VHP_U + nc * 68 + kp];
            uint32_t vh1 = smu[VHP_U + nc * 68 + kp + 4];
            MMA_F16(oacc[nt][0], oacc[nt][1], oacc[nt][2], oacc[nt][3],
                    ah0, ah1, ah2, ah3, vh0, vh1);
            MMA_F16(oacc[nt][0], oacc[nt][1], oacc[nt][2], oacc[nt][3],
                    al0, al1, al2, al3, vh0, vh1);
        }
    }

    // ---- store y (ungated): C-layout float2 pairs ----
    const size_t obase = ((size_t)(b * HW_) + (size_t)h * W_) * C_ + n * HD_;
    const int ocol = 2 * jl;
    #pragma unroll
    for (int nt = 0; nt < 4; ++nt) {
        float2 p1; p1.x = oacc[nt][0]; p1.y = oacc[nt][1];
        float2 p2; p2.x = oacc[nt][2]; p2.y = oacc[nt][3];
        *(float2*)(g_y + obase + (size_t)r1 * C_ + 8 * nt + ocol) = p1;
        *(float2*)(g_y + obase + (size_t)r2 * C_ + 8 * nt + ocol) = p2;
    }
}

// ---------------------------------------------------------------------------
// Gate: mean |attn| per window, global max, M = max(mean/max, 0.5).
// Resets g_wsum for the next graph replay.
// ---------------------------------------------------------------------------
__global__ void gate_kernel() {
    __shared__ float red[512];
    const int t = threadIdx.x;
    float mean = g_wsum[t] * (1.0f / 131072.0f);   // / (NH*W*W)
    g_wsum[t] = 0.0f;
    red[t] = mean;
    __syncthreads();
    for (int s = 256; s > 0; s >>= 1) {
        if (t < s) red[t] = fmaxf(red[t], red[t + s]);
        __syncthreads();
    }
    g_M[t] = fmaxf(mean / red[0], 0.5f);
}

// ---------------------------------------------------------------------------
// Blend: out = M * y + (1 - M) * res   (pure bandwidth, float4)
// ---------------------------------------------------------------------------
__global__ __launch_bounds__(256) void blend_kernel(const float* __restrict__ resx,
                                                    float* __restrict__ out) {
    const int i  = blockIdx.x * 256 + threadIdx.x;   // float4 index
    const int wi = i >> 13;                          // / (W_*C_/4 = 8192)
    const float Mw   = g_M[wi];
    const float oneM = 1.0f - Mw;
    float4 y = ((const float4*)g_y)[i];
    float4 r = ((const float4*)resx)[i];
    float4 o;
    o.x = fmaf(Mw, y.x, oneM * r.x);
    o.y = fmaf(Mw, y.y, oneM * r.y);
    o.z = fmaf(Mw, y.z, oneM * r.z);
    o.w = fmaf(Mw, y.w, oneM * r.w);
    ((float4*)out)[i] = o;
}

// ---------------------------------------------------------------------------
extern "C" void kernel_launch(void* const* d_in, const int* in_sizes, int n_in,
                              void* d_out, int out_size) {
    (void)in_sizes; (void)n_in; (void)out_size;
    const float* qkv  = (const float*)d_in[0];
    const float* resx = (const float*)d_in[1];
    float* out = (float*)d_out;

    cudaFuncSetAttribute(fused_kernel, cudaFuncAttributeMaxDynamicSharedMemorySize,
                         FUSED_SMEM);

    fused_kernel<<<NCTA, 256, FUSED_SMEM>>>(qkv);
    gate_kernel<<<1, NWIN>>>();
    blend_kernel<<<(B_ * HW_ * C_ / 4) / 256, 256>>>(resx, out);
}

// round 9
// speedup vs baseline: 2.2717x; 1.0791x over previous
#include <cuda_runtime.h>
#include <cuda_fp16.h>
#include <math.h>
#include <cstdint>

// Problem constants
#define B_    4
#define H_    128
#define W_    128
#define C_    256
#define NH_   8
#define HD_   32
#define HW_   (H_ * W_)                 // 16384
#define NWIN  (B_ * H_)                 // 512
#define NCTA  (NWIN * NH_)              // 4096
#define QKV_STRIDE ((size_t)B_ * HW_ * C_)

// Scratch: ungated attention output y in fp16 (33.5 MB)
__device__ __align__(16) __half g_yh[(size_t)B_ * HW_ * C_];
__device__ float g_wsum[NWIN];
__device__ float g_M[NWIN];

// ---------------- fp16 m16n8k16 mma.sync (sm_80+ baseline) ----------------
#define MMA_F16(c0, c1, c2, c3, a0, a1, a2, a3, b0, b1) \
    asm volatile("mma.sync.aligned.m16n8k16.row.col.f32.f16.f16.f32 " \
        "{%0,%1,%2,%3}, {%4,%5,%6,%7}, {%8,%9}, {%0,%1,%2,%3};" \
        : "+f"(c0), "+f"(c1), "+f"(c2), "+f"(c3) \
        : "r"(a0), "r"(a1), "r"(a2), "r"(a3), "r"(b0), "r"(b1))

#define LDSM_X4(r0, r1, r2, r3, addr) \
    asm volatile("ldmatrix.sync.aligned.m8n8.x4.shared.b16 {%0,%1,%2,%3}, [%4];" \
        : "=r"(r0), "=r"(r1), "=r"(r2), "=r"(r3) : "r"(addr))

__device__ __forceinline__ uint32_t h2u(__half2 h) { return *(uint32_t*)&h; }
__device__ __forceinline__ uint32_t smem_u32(const void* p) {
    uint32_t a;
    asm("{ .reg .u64 t; cvta.to.shared.u64 t, %1; cvt.u32.u64 %0, t; }"
        : "=r"(a) : "l"(p));
    return a;
}

// ---------------- fused kernel smem layout (u32 word offsets) --------------
// QHP/QLP: [128 rows][20 stride] fp16x2 d-pairs (Q hi + residual planes)
// KHP:     [128 rows][20 stride] fp16x2 d-pairs (single plane)
// VHP:     [32 d-rows][68 stride] fp16x2 k-pairs (single plane, transposed)
// SCT:     float2[128] {sin(k*pi/127), cos(k*pi/127)}
#define QHP_U      0
#define QLP_U      2560
#define KHP_U      5120
#define VHP_U      7680
#define SCT_U      9856
#define WS_U       10112
#define SMEM_WORDS 10120
#define FUSED_SMEM (SMEM_WORDS * 4)    // 40,480 bytes

#define A127 (3.14159265358979323846f / 127.0f)

// ---------------------------------------------------------------------------
// Fused kernel, per (window, head):
//   1. stage Q (2-plane fp16), K (1-plane), V (1-plane, transposed) in smem
//   2. QK^T: (Qh+Ql)*Kh, 2 mmas per k16; fragments via ldmatrix.x4
//   3. bias via exact identity 2*sin((k-q)pi/127), |.| sums, row L2 norm,
//      1-cos in registers
//   4. AV: A 2-plane fp16 repack of C tiles; V fragments via ldmatrix.x4
//   5. store ungated y as fp16 (gate M applied in blend kernel)
// ---------------------------------------------------------------------------
__global__ __launch_bounds__(256, 2) void fused_kernel(const float* __restrict__ qkv) {
    extern __shared__ uint32_t smu[];
    float* smf = (float*)smu;

    const int bx  = blockIdx.x;        // 0..4095
    const int wi  = bx >> 3;
    const int n   = bx & 7;
    const int b   = wi >> 7;
    const int h   = wi & 127;
    const int tid = threadIdx.x;
    const int wid = tid >> 5;
    const int lane = tid & 31;

    // sincos table for the RPE bias identity
    if (tid < 128) {
        float a = (float)tid * A127;
        smf[SCT_U + 2 * tid]     = sinf(a);
        smf[SCT_U + 2 * tid + 1] = cosf(a);
    }

    const float* qb = qkv + ((size_t)(b * HW_) + (size_t)h * W_) * C_ + n * HD_;
    const float* kb = qb + QKV_STRIDE;
    const float* vb = kb + QKV_STRIDE;

    // Stage Q (split fp16) and K (single fp16): packed d-pairs, row stride 20
    #pragma unroll
    for (int t = 0; t < 4; ++t) {
        int idx = tid + t * 256;       // 1024 float4 chunks
        int w   = idx >> 3;            // row 0..127
        int d4  = (idx & 7) << 2;      // 0,4,...,28
        float4 qv = *(const float4*)(qb + (size_t)w * C_ + d4);
        float4 kv = *(const float4*)(kb + (size_t)w * C_ + d4);
        int base = w * 20 + (d4 >> 1);
        __half2 qh0 = __floats2half2_rn(qv.x, qv.y);
        __half2 qh1 = __floats2half2_rn(qv.z, qv.w);
        float2 qb0 = __half22float2(qh0);
        float2 qb1 = __half22float2(qh1);
        __half2 ql0 = __floats2half2_rn(qv.x - qb0.x, qv.y - qb0.y);
        __half2 ql1 = __floats2half2_rn(qv.z - qb1.x, qv.w - qb1.y);
        smu[QHP_U + base] = h2u(qh0);  smu[QHP_U + base + 1] = h2u(qh1);
        smu[QLP_U + base] = h2u(ql0);  smu[QLP_U + base + 1] = h2u(ql1);
        smu[KHP_U + base]     = h2u(__floats2half2_rn(kv.x, kv.y));
        smu[KHP_U + base + 1] = h2u(__floats2half2_rn(kv.z, kv.w));
    }
    // Stage V transposed (single fp16): VHP[d][k-pair]
    #pragma unroll
    for (int t = 0; t < 8; ++t) {
        int idx = tid + t * 256;       // 2048 items
        int d   = idx & 31;
        int w2  = idx >> 5;            // 0..63
        float v0 = vb[(size_t)(2 * w2)     * C_ + d];
        float v1 = vb[(size_t)(2 * w2 + 1) * C_ + d];
        smu[VHP_U + d * 68 + w2] = h2u(__floats2half2_rn(v0, v1));
    }
    __syncthreads();

    // ldmatrix per-lane base addresses (bytes)
    const uint32_t smb = smem_u32(smu);
    // A-frag (Q): bit3 -> +8 rows, bit4 -> +4 words
    const uint32_t qrow  = 16 * wid + (lane & 7) + 8 * ((lane >> 3) & 1);
    const uint32_t qaddr = smb + 4 * (QHP_U + qrow * 20 + 4 * ((lane >> 4) & 1));
    const uint32_t qladd = qaddr + 4 * (QLP_U - QHP_U);
    // B-frag (K): bit4 -> +8 rows (odd nt), bit3 -> +4 words (second frag)
    const uint32_t krow  = (lane & 7) + 8 * ((lane >> 4) & 1);
    const uint32_t kaddr = smb + 4 * (KHP_U + krow * 20 + 4 * ((lane >> 3) & 1));
    // B-frag (V): same pattern, stride 68 words = 272 bytes
    const uint32_t vaddr = smb + 4 * (VHP_U + krow * 68 + 4 * ((lane >> 3) & 1));

    // ---- QK^T: warp wid -> rows 16*wid..16*wid+15, 2 chunks of k16 ----
    float c[16][4];
    #pragma unroll
    for (int nt = 0; nt < 16; ++nt)
        #pragma unroll
        for (int j = 0; j < 4; ++j) c[nt][j] = 0.0f;

    const int arow = 16 * wid + (lane >> 2);
    const int jl   = lane & 3;
    #pragma unroll
    for (int ch = 0; ch < 2; ++ch) {
        uint32_t qh0, qh1, qh2, qh3, ql0, ql1, ql2, ql3;
        LDSM_X4(qh0, qh1, qh2, qh3, qaddr + ch * 32);
        LDSM_X4(ql0, ql1, ql2, ql3, qladd + ch * 32);
        #pragma unroll
        for (int t = 0; t < 8; ++t) {
            uint32_t k00, k01, k10, k11;
            LDSM_X4(k00, k01, k10, k11, kaddr + t * 1280 + ch * 32);  // 16 rows * 80B
            MMA_F16(c[2*t][0], c[2*t][1], c[2*t][2], c[2*t][3],
                    qh0, qh1, qh2, qh3, k00, k01);
            MMA_F16(c[2*t][0], c[2*t][1], c[2*t][2], c[2*t][3],
                    ql0, ql1, ql2, ql3, k00, k01);
            MMA_F16(c[2*t+1][0], c[2*t+1][1], c[2*t+1][2], c[2*t+1][3],
                    qh0, qh1, qh2, qh3, k10, k11);
            MMA_F16(c[2*t+1][0], c[2*t+1][1], c[2*t+1][2], c[2*t+1][3],
                    ql0, ql1, ql2, ql3, k10, k11);
        }
    }

    // ---- epilogue: bias = bs2*sin((k-q)*pi/127) via sincos identity ----
    const int r1 = arow;
    const int r2 = arow + 8;
    const float bs2 = 0.2f * sinf((float)h * (3.14159265358979323846f / 128.0f));
    const float f1c = bs2 * cosf((float)r1 * A127);
    const float f1s = bs2 * sinf((float)r1 * A127);
    const float f2c = bs2 * cosf((float)r2 * A127);
    const float f2s = bs2 * sinf((float)r2 * A127);

    float sq1 = 0.0f, sq2 = 0.0f, s_abs = 0.0f;
    #pragma unroll
    for (int nt = 0; nt < 16; ++nt) {
        const int col0 = 8 * nt + 2 * jl;
        float4 t = *(const float4*)(smf + SCT_U + 2 * col0);   // {s0,c0,s1,c1}
        float v0 = c[nt][0] + (t.x * f1c - t.y * f1s);
        float v1 = c[nt][1] + (t.z * f1c - t.w * f1s);
        float v2 = c[nt][2] + (t.x * f2c - t.y * f2s);
        float v3 = c[nt][3] + (t.z * f2c - t.w * f2s);
        c[nt][0] = v0; c[nt][1] = v1; c[nt][2] = v2; c[nt][3] = v3;
        sq1 += v0 * v0 + v1 * v1;
        sq2 += v2 * v2 + v3 * v3;
        s_abs += fabsf(v0) + fabsf(v1) + fabsf(v2) + fabsf(v3);
    }
    sq1 += __shfl_xor_sync(0xffffffffu, sq1, 1);
    sq1 += __shfl_xor_sync(0xffffffffu, sq1, 2);
    sq2 += __shfl_xor_sync(0xffffffffu, sq2, 1);
    sq2 += __shfl_xor_sync(0xffffffffu, sq2, 2);
    #pragma unroll
    for (int m = 16; m; m >>= 1)
        s_abs += __shfl_xor_sync(0xffffffffu, s_abs, m);
    if (lane == 0) smf[WS_U + wid] = s_abs;

    // ---- transform in registers: c <- 1 - cos(v * (pi/2)/norm) ----
    {
        const float inv1 = 1.57079632679489662f / fmaxf(sqrtf(sq1), 1e-12f);
        const float inv2 = 1.57079632679489662f / fmaxf(sqrtf(sq2), 1e-12f);
        #pragma unroll
        for (int nt = 0; nt < 16; ++nt) {
            c[nt][0] = 1.0f - __cosf(c[nt][0] * inv1);
            c[nt][1] = 1.0f - __cosf(c[nt][1] * inv1);
            c[nt][2] = 1.0f - __cosf(c[nt][2] * inv2);
            c[nt][3] = 1.0f - __cosf(c[nt][3] * inv2);
        }
    }

    __syncthreads();   // WS visible
    if (tid == 0) {
        float s = 0.0f;
        #pragma unroll
        for (int i = 0; i < 8; ++i) s += smf[WS_U + i];
        atomicAdd(&g_wsum[wi], s);
    }

    // ---- AV: A = 2-plane fp16 repack of C tiles; V frags via ldmatrix ----
    float oacc[4][4];
    #pragma unroll
    for (int nt = 0; nt < 4; ++nt)
        #pragma unroll
        for (int j = 0; j < 4; ++j) oacc[nt][j] = 0.0f;

    #pragma unroll
    for (int ch = 0; ch < 8; ++ch) {
        __half2 ha0 = __floats2half2_rn(c[2 * ch][0],     c[2 * ch][1]);
        __half2 ha1 = __floats2half2_rn(c[2 * ch][2],     c[2 * ch][3]);
        __half2 ha2 = __floats2half2_rn(c[2 * ch + 1][0], c[2 * ch + 1][1]);
        __half2 ha3 = __floats2half2_rn(c[2 * ch + 1][2], c[2 * ch + 1][3]);
        float2 b0 = __half22float2(ha0);
        float2 b1 = __half22float2(ha1);
        float2 b2 = __half22float2(ha2);
        float2 b3 = __half22float2(ha3);
        __half2 la0 = __floats2half2_rn(c[2 * ch][0] - b0.x,     c[2 * ch][1] - b0.y);
        __half2 la1 = __floats2half2_rn(c[2 * ch][2] - b1.x,     c[2 * ch][3] - b1.y);
        __half2 la2 = __floats2half2_rn(c[2 * ch + 1][0] - b2.x, c[2 * ch + 1][1] - b2.y);
        __half2 la3 = __floats2half2_rn(c[2 * ch + 1][2] - b3.x, c[2 * ch + 1][3] - b3.y);
        uint32_t ah0 = h2u(ha0), ah1 = h2u(ha1), ah2 = h2u(ha2), ah3 = h2u(ha3);
        uint32_t al0 = h2u(la0), al1 = h2u(la1), al2 = h2u(la2), al3 = h2u(la3);

        uint32_t v00, v01, v10, v11, v20, v21, v30, v31;
        LDSM_X4(v00, v01, v10, v11, vaddr + ch * 32);               // d rows 0-15
        LDSM_X4(v20, v21, v30, v31, vaddr + 16 * 272 + ch * 32);    // d rows 16-31
        MMA_F16(oacc[0][0], oacc[0][1], oacc[0][2], oacc[0][3],
                ah0, ah1, ah2, ah3, v00, v01);
        MMA_F16(oacc[0][0], oacc[0][1], oacc[0][2], oacc[0][3],
                al0, al1, al2, al3, v00, v01);
        MMA_F16(oacc[1][0], oacc[1][1], oacc[1][2], oacc[1][3],
                ah0, ah1, ah2, ah3, v10, v11);
        MMA_F16(oacc[1][0], oacc[1][1], oacc[1][2], oacc[1][3],
                al0, al1, al2, al3, v10, v11);
        MMA_F16(oacc[2][0], oacc[2][1], oacc[2][2], oacc[2][3],
                ah0, ah1, ah2, ah3, v20, v21);
        MMA_F16(oacc[2][0], oacc[2][1], oacc[2][2], oacc[2][3],
                al0, al1, al2, al3, v20, v21);
        MMA_F16(oacc[3][0], oacc[3][1], oacc[3][2], oacc[3][3],
                ah0, ah1, ah2, ah3, v30, v31);
        MMA_F16(oacc[3][0], oacc[3][1], oacc[3][2], oacc[3][3],
                al0, al1, al2, al3, v30, v31);
    }

    // ---- store y (ungated) as fp16: C-layout half2 pairs ----
    const size_t obase = ((size_t)(b * HW_) + (size_t)h * W_) * C_ + n * HD_;
    const int ocol = 2 * jl;
    #pragma unroll
    for (int nt = 0; nt < 4; ++nt) {
        __half2 p1 = __floats2half2_rn(oacc[nt][0], oacc[nt][1]);
        __half2 p2 = __floats2half2_rn(oacc[nt][2], oacc[nt][3]);
        *(__half2*)(g_yh + obase + (size_t)r1 * C_ + 8 * nt + ocol) = p1;
        *(__half2*)(g_yh + obase + (size_t)r2 * C_ + 8 * nt + ocol) = p2;
    }
}

// ---------------------------------------------------------------------------
// Gate: mean |attn| per window, global max, M = max(mean/max, 0.5).
// Resets g_wsum for the next graph replay.
// ---------------------------------------------------------------------------
__global__ void gate_kernel() {
    __shared__ float red[512];
    const int t = threadIdx.x;
    float mean = g_wsum[t] * (1.0f / 131072.0f);   // / (NH*W*W)
    g_wsum[t] = 0.0f;
    red[t] = mean;
    __syncthreads();
    for (int s = 256; s > 0; s >>= 1) {
        if (t < s) red[t] = fmaxf(red[t], red[t + s]);
        __syncthreads();
    }
    g_M[t] = fmaxf(mean / red[0], 0.5f);
}

// ---------------------------------------------------------------------------
// Blend: out = M * y + (1 - M) * res   (pure bandwidth)
// ---------------------------------------------------------------------------
__global__ __launch_bounds__(256) void blend_kernel(const float* __restrict__ resx,
                                                    float* __restrict__ out) {
    const int i  = blockIdx.x * 256 + threadIdx.x;   // float4 index
    const int wi = i >> 13;                          // / (W_*C_/4 = 8192)
    const float Mw   = g_M[wi];
    const float oneM = 1.0f - Mw;
    const __half2* yp = (const __half2*)g_yh + 2 * (size_t)i;
    float2 y01 = __half22float2(yp[0]);
    float2 y23 = __half22float2(yp[1]);
    float4 r = ((const float4*)resx)[i];
    float4 o;
    o.x = fmaf(Mw, y01.x, oneM * r.x);
    o.y = fmaf(Mw, y01.y, oneM * r.y);
    o.z = fmaf(Mw, y23.x, oneM * r.z);
    o.w = fmaf(Mw, y23.y, oneM * r.w);
    ((float4*)out)[i] = o;
}

// ---------------------------------------------------------------------------
extern "C" void kernel_launch(void* const* d_in, const int* in_sizes, int n_in,
                              void* d_out, int out_size) {
    (void)in_sizes; (void)n_in; (void)out_size;
    const float* qkv  = (const float*)d_in[0];
    const float* resx = (const float*)d_in[1];
    float* out = (float*)d_out;

    cudaFuncSetAttribute(fused_kernel, cudaFuncAttributeMaxDynamicSharedMemorySize,
                         FUSED_SMEM);

    fused_kernel<<<NCTA, 256, FUSED_SMEM>>>(qkv);
    gate_kernel<<<1, NWIN>>>();
    blend_kernel<<<(B_ * HW_ * C_ / 4) / 256, 256>>>(resx, out);
}

// round 10
// speedup vs baseline: 2.4182x; 1.0645x over previous
#include <cuda_runtime.h>
#include <cuda_fp16.h>
#include <math.h>
#include <cstdint>

// Problem constants
#define B_    4
#define H_    128
#define W_    128
#define C_    256
#define NH_   8
#define HD_   32
#define HW_   (H_ * W_)                 // 16384
#define NWIN  (B_ * H_)                 // 512
#define NCTA  (NWIN * NH_)              // 4096
#define QKV_STRIDE ((size_t)B_ * HW_ * C_)

// Scratch: ungated attention output y in fp16 (33.5 MB)
__device__ __align__(16) __half g_yh[(size_t)B_ * HW_ * C_];
__device__ float g_wsum[NWIN];
__device__ float g_M[NWIN];

// ---------------- fp16 m16n8k16 mma.sync (sm_80+ baseline) ----------------
#define MMA_F16(c0, c1, c2, c3, a0, a1, a2, a3, b0, b1) \
    asm volatile("mma.sync.aligned.m16n8k16.row.col.f32.f16.f16.f32 " \
        "{%0,%1,%2,%3}, {%4,%5,%6,%7}, {%8,%9}, {%0,%1,%2,%3};" \
        : "+f"(c0), "+f"(c1), "+f"(c2), "+f"(c3) \
        : "r"(a0), "r"(a1), "r"(a2), "r"(a3), "r"(b0), "r"(b1))

#define LDSM_X4(r0, r1, r2, r3, addr) \
    asm volatile("ldmatrix.sync.aligned.m8n8.x4.shared.b16 {%0,%1,%2,%3}, [%4];" \
        : "=r"(r0), "=r"(r1), "=r"(r2), "=r"(r3) : "r"(addr))

__device__ __forceinline__ uint32_t h2u(__half2 h) { return *(uint32_t*)&h; }
__device__ __forceinline__ uint32_t smem_u32(const void* p) {
    uint32_t a;
    asm("{ .reg .u64 t; cvta.to.shared.u64 t, %1; cvt.u32.u64 %0, t; }"
        : "=r"(a) : "l"(p));
    return a;
}

// ---------------- fused kernel smem layout (u32 word offsets) --------------
// QHP/QLP: [128 rows][20 stride] fp16x2 d-pairs (Q hi + residual planes)
// KHP:     [128 rows][20 stride] fp16x2 d-pairs (single plane)
// VHP:     [32 d-rows][68 stride] fp16x2 k-pairs (single plane, transposed)
// SCT:     float2[128] {sin(k*pi/127), cos(k*pi/127)}
#define QHP_U      0
#define QLP_U      2560
#define KHP_U      5120
#define VHP_U      7680
#define SCT_U      9856
#define WS_U       10112
#define SMEM_WORDS 10120
#define FUSED_SMEM (SMEM_WORDS * 4)    // 40,480 bytes

#define A127 (3.14159265358979323846f / 127.0f)

// ---------------------------------------------------------------------------
// Fused kernel, per (window, head):
//   1. stage Q (2-plane fp16), K (1-plane), V (1-plane, transposed) in smem
//   2. QK^T: (Qh+Ql)*Kh, 2 mmas per k16; fragments via ldmatrix.x4
//   3. bias via exact identity 2*sin((k-q)pi/127), |.| sums, row L2 norm,
//      1-cos in registers
//   4. AV: A single-plane fp16 repack of C tiles (weights in [0,2], eps
//      2^-11 -> ~5e-4 on y, inside budget); V fragments via ldmatrix.x4
//   5. store ungated y as fp16 (gate M applied in blend kernel)
// ---------------------------------------------------------------------------
__global__ __launch_bounds__(256, 2) void fused_kernel(const float* __restrict__ qkv) {
    extern __shared__ uint32_t smu[];
    float* smf = (float*)smu;

    const int bx  = blockIdx.x;        // 0..4095
    const int wi  = bx >> 3;
    const int n   = bx & 7;
    const int b   = wi >> 7;
    const int h   = wi & 127;
    const int tid = threadIdx.x;
    const int wid = tid >> 5;
    const int lane = tid & 31;

    // sincos table for the RPE bias identity
    if (tid < 128) {
        float a = (float)tid * A127;
        smf[SCT_U + 2 * tid]     = sinf(a);
        smf[SCT_U + 2 * tid + 1] = cosf(a);
    }

    const float* qb = qkv + ((size_t)(b * HW_) + (size_t)h * W_) * C_ + n * HD_;
    const float* kb = qb + QKV_STRIDE;
    const float* vb = kb + QKV_STRIDE;

    // Stage Q (split fp16) and K (single fp16): packed d-pairs, row stride 20
    #pragma unroll
    for (int t = 0; t < 4; ++t) {
        int idx = tid + t * 256;       // 1024 float4 chunks
        int w   = idx >> 3;            // row 0..127
        int d4  = (idx & 7) << 2;      // 0,4,...,28
        float4 qv = *(const float4*)(qb + (size_t)w * C_ + d4);
        float4 kv = *(const float4*)(kb + (size_t)w * C_ + d4);
        int base = w * 20 + (d4 >> 1);
        __half2 qh0 = __floats2half2_rn(qv.x, qv.y);
        __half2 qh1 = __floats2half2_rn(qv.z, qv.w);
        float2 qb0 = __half22float2(qh0);
        float2 qb1 = __half22float2(qh1);
        __half2 ql0 = __floats2half2_rn(qv.x - qb0.x, qv.y - qb0.y);
        __half2 ql1 = __floats2half2_rn(qv.z - qb1.x, qv.w - qb1.y);
        smu[QHP_U + base] = h2u(qh0);  smu[QHP_U + base + 1] = h2u(qh1);
        smu[QLP_U + base] = h2u(ql0);  smu[QLP_U + base + 1] = h2u(ql1);
        smu[KHP_U + base]     = h2u(__floats2half2_rn(kv.x, kv.y));
        smu[KHP_U + base + 1] = h2u(__floats2half2_rn(kv.z, kv.w));
    }
    // Stage V transposed (single fp16): VHP[d][k-pair]
    #pragma unroll
    for (int t = 0; t < 8; ++t) {
        int idx = tid + t * 256;       // 2048 items
        int d   = idx & 31;
        int w2  = idx >> 5;            // 0..63
        float v0 = vb[(size_t)(2 * w2)     * C_ + d];
        float v1 = vb[(size_t)(2 * w2 + 1) * C_ + d];
        smu[VHP_U + d * 68 + w2] = h2u(__floats2half2_rn(v0, v1));
    }
    __syncthreads();

    // ldmatrix per-lane base addresses (bytes)
    const uint32_t smb = smem_u32(smu);
    const uint32_t qrow  = 16 * wid + (lane & 7) + 8 * ((lane >> 3) & 1);
    const uint32_t qaddr = smb + 4 * (QHP_U + qrow * 20 + 4 * ((lane >> 4) & 1));
    const uint32_t qladd = qaddr + 4 * (QLP_U - QHP_U);
    const uint32_t krow  = (lane & 7) + 8 * ((lane >> 4) & 1);
    const uint32_t kaddr = smb + 4 * (KHP_U + krow * 20 + 4 * ((lane >> 3) & 1));
    const uint32_t vaddr = smb + 4 * (VHP_U + krow * 68 + 4 * ((lane >> 3) & 1));

    // ---- QK^T: warp wid -> rows 16*wid..16*wid+15, 2 chunks of k16 ----
    float c[16][4];
    #pragma unroll
    for (int nt = 0; nt < 16; ++nt)
        #pragma unroll
        for (int j = 0; j < 4; ++j) c[nt][j] = 0.0f;

    const int arow = 16 * wid + (lane >> 2);
    const int jl   = lane & 3;
    #pragma unroll
    for (int ch = 0; ch < 2; ++ch) {
        uint32_t qh0, qh1, qh2, qh3, ql0, ql1, ql2, ql3;
        LDSM_X4(qh0, qh1, qh2, qh3, qaddr + ch * 32);
        LDSM_X4(ql0, ql1, ql2, ql3, qladd + ch * 32);
        #pragma unroll
        for (int t = 0; t < 8; ++t) {
            uint32_t k00, k01, k10, k11;
            LDSM_X4(k00, k01, k10, k11, kaddr + t * 1280 + ch * 32);  // 16 rows * 80B
            MMA_F16(c[2*t][0], c[2*t][1], c[2*t][2], c[2*t][3],
                    qh0, qh1, qh2, qh3, k00, k01);
            MMA_F16(c[2*t][0], c[2*t][1], c[2*t][2], c[2*t][3],
                    ql0, ql1, ql2, ql3, k00, k01);
            MMA_F16(c[2*t+1][0], c[2*t+1][1], c[2*t+1][2], c[2*t+1][3],
                    qh0, qh1, qh2, qh3, k10, k11);
            MMA_F16(c[2*t+1][0], c[2*t+1][1], c[2*t+1][2], c[2*t+1][3],
                    ql0, ql1, ql2, ql3, k10, k11);
        }
    }

    // ---- epilogue: bias = bs2*sin((k-q)*pi/127) via sincos identity ----
    const int r1 = arow;
    const int r2 = arow + 8;
    const float bs2 = 0.2f * sinf((float)h * (3.14159265358979323846f / 128.0f));
    const float f1c = bs2 * cosf((float)r1 * A127);
    const float f1s = bs2 * sinf((float)r1 * A127);
    const float f2c = bs2 * cosf((float)r2 * A127);
    const float f2s = bs2 * sinf((float)r2 * A127);

    float sq1 = 0.0f, sq2 = 0.0f, s_abs = 0.0f;
    #pragma unroll
    for (int nt = 0; nt < 16; ++nt) {
        const int col0 = 8 * nt + 2 * jl;
        float4 t = *(const float4*)(smf + SCT_U + 2 * col0);   // {s0,c0,s1,c1}
        float v0 = c[nt][0] + (t.x * f1c - t.y * f1s);
        float v1 = c[nt][1] + (t.z * f1c - t.w * f1s);
        float v2 = c[nt][2] + (t.x * f2c - t.y * f2s);
        float v3 = c[nt][3] + (t.z * f2c - t.w * f2s);
        c[nt][0] = v0; c[nt][1] = v1; c[nt][2] = v2; c[nt][3] = v3;
        sq1 += v0 * v0 + v1 * v1;
        sq2 += v2 * v2 + v3 * v3;
        s_abs += fabsf(v0) + fabsf(v1) + fabsf(v2) + fabsf(v3);
    }
    sq1 += __shfl_xor_sync(0xffffffffu, sq1, 1);
    sq1 += __shfl_xor_sync(0xffffffffu, sq1, 2);
    sq2 += __shfl_xor_sync(0xffffffffu, sq2, 1);
    sq2 += __shfl_xor_sync(0xffffffffu, sq2, 2);
    #pragma unroll
    for (int m = 16; m; m >>= 1)
        s_abs += __shfl_xor_sync(0xffffffffu, s_abs, m);
    if (lane == 0) smf[WS_U + wid] = s_abs;

    // ---- transform in registers: c <- 1 - cos(v * (pi/2)/norm) ----
    {
        const float inv1 = 1.57079632679489662f / fmaxf(sqrtf(sq1), 1e-12f);
        const float inv2 = 1.57079632679489662f / fmaxf(sqrtf(sq2), 1e-12f);
        #pragma unroll
        for (int nt = 0; nt < 16; ++nt) {
            c[nt][0] = 1.0f - __cosf(c[nt][0] * inv1);
            c[nt][1] = 1.0f - __cosf(c[nt][1] * inv1);
            c[nt][2] = 1.0f - __cosf(c[nt][2] * inv2);
            c[nt][3] = 1.0f - __cosf(c[nt][3] * inv2);
        }
    }

    __syncthreads();   // WS visible
    if (tid == 0) {
        float s = 0.0f;
        #pragma unroll
        for (int i = 0; i < 8; ++i) s += smf[WS_U + i];
        atomicAdd(&g_wsum[wi], s);
    }

    // ---- AV: A = single-plane fp16 repack of C tiles; V via ldmatrix ----
    float oacc[4][4];
    #pragma unroll
    for (int nt = 0; nt < 4; ++nt)
        #pragma unroll
        for (int j = 0; j < 4; ++j) oacc[nt][j] = 0.0f;

    #pragma unroll
    for (int ch = 0; ch < 8; ++ch) {
        uint32_t ah0 = h2u(__floats2half2_rn(c[2 * ch][0],     c[2 * ch][1]));
        uint32_t ah1 = h2u(__floats2half2_rn(c[2 * ch][2],     c[2 * ch][3]));
        uint32_t ah2 = h2u(__floats2half2_rn(c[2 * ch + 1][0], c[2 * ch + 1][1]));
        uint32_t ah3 = h2u(__floats2half2_rn(c[2 * ch + 1][2], c[2 * ch + 1][3]));

        uint32_t v00, v01, v10, v11, v20, v21, v30, v31;
        LDSM_X4(v00, v01, v10, v11, vaddr + ch * 32);               // d rows 0-15
        LDSM_X4(v20, v21, v30, v31, vaddr + 16 * 272 + ch * 32);    // d rows 16-31
        MMA_F16(oacc[0][0], oacc[0][1], oacc[0][2], oacc[0][3],
                ah0, ah1, ah2, ah3, v00, v01);
        MMA_F16(oacc[1][0], oacc[1][1], oacc[1][2], oacc[1][3],
                ah0, ah1, ah2, ah3, v10, v11);
        MMA_F16(oacc[2][0], oacc[2][1], oacc[2][2], oacc[2][3],
                ah0, ah1, ah2, ah3, v20, v21);
        MMA_F16(oacc[3][0], oacc[3][1], oacc[3][2], oacc[3][3],
                ah0, ah1, ah2, ah3, v30, v31);
    }

    // ---- store y (ungated) as fp16: C-layout half2 pairs ----
    const size_t obase = ((size_t)(b * HW_) + (size_t)h * W_) * C_ + n * HD_;
    const int ocol = 2 * jl;
    #pragma unroll
    for (int nt = 0; nt < 4; ++nt) {
        __half2 p1 = __floats2half2_rn(oacc[nt][0], oacc[nt][1]);
        __half2 p2 = __floats2half2_rn(oacc[nt][2], oacc[nt][3]);
        *(__half2*)(g_yh + obase + (size_t)r1 * C_ + 8 * nt + ocol) = p1;
        *(__half2*)(g_yh + obase + (size_t)r2 * C_ + 8 * nt + ocol) = p2;
    }
}

// ---------------------------------------------------------------------------
// Gate: mean |attn| per window, global max, M = max(mean/max, 0.5).
// Resets g_wsum for the next graph replay.
// ---------------------------------------------------------------------------
__global__ void gate_kernel() {
    __shared__ float red[512];
    const int t = threadIdx.x;
    float mean = g_wsum[t] * (1.0f / 131072.0f);   // / (NH*W*W)
    g_wsum[t] = 0.0f;
    red[t] = mean;
    __syncthreads();
    for (int s = 256; s > 0; s >>= 1) {
        if (t < s) red[t] = fmaxf(red[t], red[t + s]);
        __syncthreads();
    }
    g_M[t] = fmaxf(mean / red[0], 0.5f);
}

// ---------------------------------------------------------------------------
// Blend: out = M * y + (1 - M) * res   (pure bandwidth)
// ---------------------------------------------------------------------------
__global__ __launch_bounds__(256) void blend_kernel(const float* __restrict__ resx,
                                                    float* __restrict__ out) {
    const int i  = blockIdx.x * 256 + threadIdx.x;   // float4 index
    const int wi = i >> 13;                          // / (W_*C_/4 = 8192)
    const float Mw   = g_M[wi];
    const float oneM = 1.0f - Mw;
    const __half2* yp = (const __half2*)g_yh + 2 * (size_t)i;
    float2 y01 = __half22float2(yp[0]);
    float2 y23 = __half22float2(yp[1]);
    float4 r = ((const float4*)resx)[i];
    float4 o;
    o.x = fmaf(Mw, y01.x, oneM * r.x);
    o.y = fmaf(Mw, y01.y, oneM * r.y);
    o.z = fmaf(Mw, y23.x, oneM * r.z);
    o.w = fmaf(Mw, y23.y, oneM * r.w);
    ((float4*)out)[i] = o;
}

// ---------------------------------------------------------------------------
extern "C" void kernel_launch(void* const* d_in, const int* in_sizes, int n_in,
                              void* d_out, int out_size) {
    (void)in_sizes; (void)n_in; (void)out_size;
    const float* qkv  = (const float*)d_in[0];
    const float* resx = (const float*)d_in[1];
    float* out = (float*)d_out;

    cudaFuncSetAttribute(fused_kernel, cudaFuncAttributeMaxDynamicSharedMemorySize,
                         FUSED_SMEM);

    fused_kernel<<<NCTA, 256, FUSED_SMEM>>>(qkv);
    gate_kernel<<<1, NWIN>>>();
    blend_kernel<<<(B_ * HW_ * C_ / 4) / 256, 256>>>(resx, out);
}

// round 11
// speedup vs baseline: 2.5241x; 1.0438x over previous
#include <cuda_runtime.h>
#include <cuda_fp16.h>
#include <math.h>
#include <cstdint>

// Problem constants
#define B_    4
#define H_    128
#define W_    128
#define C_    256
#define NH_   8
#define HD_   32
#define HW_   (H_ * W_)                 // 16384
#define NWIN  (B_ * H_)                 // 512
#define NCTA  (NWIN * NH_)              // 4096
#define QKV_STRIDE ((size_t)B_ * HW_ * C_)

// Scratch: ungated attention output y in fp16 (33.5 MB)
__device__ __align__(16) __half g_yh[(size_t)B_ * HW_ * C_];
__device__ float g_wsum[NWIN];
__device__ float g_M[NWIN];

// ---------------- fp16 m16n8k16 mma.sync (sm_80+ baseline) ----------------
#define MMA_F16(c0, c1, c2, c3, a0, a1, a2, a3, b0, b1) \
    asm volatile("mma.sync.aligned.m16n8k16.row.col.f32.f16.f16.f32 " \
        "{%0,%1,%2,%3}, {%4,%5,%6,%7}, {%8,%9}, {%0,%1,%2,%3};" \
        : "+f"(c0), "+f"(c1), "+f"(c2), "+f"(c3) \
        : "r"(a0), "r"(a1), "r"(a2), "r"(a3), "r"(b0), "r"(b1))

#define LDSM_X4(r0, r1, r2, r3, addr) \
    asm volatile("ldmatrix.sync.aligned.m8n8.x4.shared.b16 {%0,%1,%2,%3}, [%4];" \
        : "=r"(r0), "=r"(r1), "=r"(r2), "=r"(r3) : "r"(addr))

__device__ __forceinline__ uint32_t h2u(__half2 h) { return *(uint32_t*)&h; }
__device__ __forceinline__ uint32_t smem_u32(const void* p) {
    uint32_t a;
    asm("{ .reg .u64 t; cvta.to.shared.u64 t, %1; cvt.u32.u64 %0, t; }"
        : "=r"(a) : "l"(p));
    return a;
}

// ---------------- fused kernel smem layout (u32 word offsets) --------------
// QHP: [128 rows][20 stride] fp16x2 d-pairs (single plane)
// KHP: [128 rows][20 stride] fp16x2 d-pairs (single plane)
// VHP: [32 d-rows][68 stride] fp16x2 k-pairs (single plane, transposed)
// SCT: float2[128] {sin(k*pi/127), cos(k*pi/127)}
#define QHP_U      0
#define KHP_U      2560
#define VHP_U      5120
#define SCT_U      7296
#define WS_U       7552
#define SMEM_WORDS 7560
#define FUSED_SMEM (SMEM_WORDS * 4)    // 30,240 bytes

#define A127 (3.14159265358979323846f / 127.0f)

// ---------------------------------------------------------------------------
// Fused kernel, per (window, head):
//   1. stage Q/K/V single-plane fp16 in smem (V transposed)
//   2. init mma accumulators with the RPE bias (2*sin((k-q)pi/127) identity)
//   3. QK^T: 1 mma per k16 tile -- bias comes out pre-added
//   4. |.| sums, per-row L2 norm (intra-warp), 1-cos in registers
//   5. AV: A single-plane fp16 repack of C tiles; V fragments via ldmatrix
//   6. store ungated y as fp16 (gate M applied in blend kernel)
// ---------------------------------------------------------------------------
__global__ __launch_bounds__(256, 2) void fused_kernel(const float* __restrict__ qkv) {
    extern __shared__ uint32_t smu[];
    float* smf = (float*)smu;

    const int bx  = blockIdx.x;        // 0..4095
    const int wi  = bx >> 3;
    const int n   = bx & 7;
    const int b   = wi >> 7;
    const int h   = wi & 127;
    const int tid = threadIdx.x;
    const int wid = tid >> 5;
    const int lane = tid & 31;

    // sincos table for the RPE bias identity
    if (tid < 128) {
        float a = (float)tid * A127;
        smf[SCT_U + 2 * tid]     = sinf(a);
        smf[SCT_U + 2 * tid + 1] = cosf(a);
    }

    const float* qb = qkv + ((size_t)(b * HW_) + (size_t)h * W_) * C_ + n * HD_;
    const float* kb = qb + QKV_STRIDE;
    const float* vb = kb + QKV_STRIDE;

    // Stage Q and K (single fp16 plane): packed d-pairs, row stride 20
    #pragma unroll
    for (int t = 0; t < 4; ++t) {
        int idx = tid + t * 256;       // 1024 float4 chunks
        int w   = idx >> 3;            // row 0..127
        int d4  = (idx & 7) << 2;      // 0,4,...,28
        float4 qv = *(const float4*)(qb + (size_t)w * C_ + d4);
        float4 kv = *(const float4*)(kb + (size_t)w * C_ + d4);
        int base = w * 20 + (d4 >> 1);
        smu[QHP_U + base]     = h2u(__floats2half2_rn(qv.x, qv.y));
        smu[QHP_U + base + 1] = h2u(__floats2half2_rn(qv.z, qv.w));
        smu[KHP_U + base]     = h2u(__floats2half2_rn(kv.x, kv.y));
        smu[KHP_U + base + 1] = h2u(__floats2half2_rn(kv.z, kv.w));
    }
    // Stage V transposed (single fp16): VHP[d][k-pair]
    #pragma unroll
    for (int t = 0; t < 8; ++t) {
        int idx = tid + t * 256;       // 2048 items
        int d   = idx & 31;
        int w2  = idx >> 5;            // 0..63
        float v0 = vb[(size_t)(2 * w2)     * C_ + d];
        float v1 = vb[(size_t)(2 * w2 + 1) * C_ + d];
        smu[VHP_U + d * 68 + w2] = h2u(__floats2half2_rn(v0, v1));
    }
    __syncthreads();

    // ldmatrix per-lane base addresses (bytes)
    const uint32_t smb = smem_u32(smu);
    const uint32_t qrow  = 16 * wid + (lane & 7) + 8 * ((lane >> 3) & 1);
    const uint32_t qaddr = smb + 4 * (QHP_U + qrow * 20 + 4 * ((lane >> 4) & 1));
    const uint32_t krow  = (lane & 7) + 8 * ((lane >> 4) & 1);
    const uint32_t kaddr = smb + 4 * (KHP_U + krow * 20 + 4 * ((lane >> 3) & 1));
    const uint32_t vaddr = smb + 4 * (VHP_U + krow * 68 + 4 * ((lane >> 3) & 1));

    const int arow = 16 * wid + (lane >> 2);
    const int jl   = lane & 3;
    const int r1 = arow;
    const int r2 = arow + 8;

    // ---- init accumulators with RPE bias: bias = bs2*sin((col-row)*pi/127)
    const float bs2 = 0.2f * sinf((float)h * (3.14159265358979323846f / 128.0f));
    const float f1c = bs2 * cosf((float)r1 * A127);
    const float f1s = bs2 * sinf((float)r1 * A127);
    const float f2c = bs2 * cosf((float)r2 * A127);
    const float f2s = bs2 * sinf((float)r2 * A127);

    float c[16][4];
    #pragma unroll
    for (int nt = 0; nt < 16; ++nt) {
        const int col0 = 8 * nt + 2 * jl;
        float4 t = *(const float4*)(smf + SCT_U + 2 * col0);   // {s0,c0,s1,c1}
        c[nt][0] = t.x * f1c - t.y * f1s;
        c[nt][1] = t.z * f1c - t.w * f1s;
        c[nt][2] = t.x * f2c - t.y * f2s;
        c[nt][3] = t.z * f2c - t.w * f2s;
    }

    // ---- QK^T: warp wid -> rows 16*wid..16*wid+15, 2 chunks of k16 ----
    #pragma unroll
    for (int ch = 0; ch < 2; ++ch) {
        uint32_t qh0, qh1, qh2, qh3;
        LDSM_X4(qh0, qh1, qh2, qh3, qaddr + ch * 32);
        #pragma unroll
        for (int t = 0; t < 8; ++t) {
            uint32_t k00, k01, k10, k11;
            LDSM_X4(k00, k01, k10, k11, kaddr + t * 1280 + ch * 32);  // 16 rows * 80B
            MMA_F16(c[2*t][0], c[2*t][1], c[2*t][2], c[2*t][3],
                    qh0, qh1, qh2, qh3, k00, k01);
            MMA_F16(c[2*t+1][0], c[2*t+1][1], c[2*t+1][2], c[2*t+1][3],
                    qh0, qh1, qh2, qh3, k10, k11);
        }
    }

    // ---- epilogue: |.| sums + row sumsq (bias already inside c) ----
    float sq1 = 0.0f, sq2 = 0.0f, s_abs = 0.0f;
    #pragma unroll
    for (int nt = 0; nt < 16; ++nt) {
        sq1 += c[nt][0] * c[nt][0] + c[nt][1] * c[nt][1];
        sq2 += c[nt][2] * c[nt][2] + c[nt][3] * c[nt][3];
        s_abs += fabsf(c[nt][0]) + fabsf(c[nt][1]) + fabsf(c[nt][2]) + fabsf(c[nt][3]);
    }
    sq1 += __shfl_xor_sync(0xffffffffu, sq1, 1);
    sq1 += __shfl_xor_sync(0xffffffffu, sq1, 2);
    sq2 += __shfl_xor_sync(0xffffffffu, sq2, 1);
    sq2 += __shfl_xor_sync(0xffffffffu, sq2, 2);
    #pragma unroll
    for (int m = 16; m; m >>= 1)
        s_abs += __shfl_xor_sync(0xffffffffu, s_abs, m);
    if (lane == 0) smf[WS_U + wid] = s_abs;

    // ---- transform in registers: c <- 1 - cos(v * (pi/2)/norm) ----
    {
        const float inv1 = 1.57079632679489662f / fmaxf(sqrtf(sq1), 1e-12f);
        const float inv2 = 1.57079632679489662f / fmaxf(sqrtf(sq2), 1e-12f);
        #pragma unroll
        for (int nt = 0; nt < 16; ++nt) {
            c[nt][0] = 1.0f - __cosf(c[nt][0] * inv1);
            c[nt][1] = 1.0f - __cosf(c[nt][1] * inv1);
            c[nt][2] = 1.0f - __cosf(c[nt][2] * inv2);
            c[nt][3] = 1.0f - __cosf(c[nt][3] * inv2);
        }
    }

    __syncthreads();   // WS visible
    if (tid == 0) {
        float s = 0.0f;
        #pragma unroll
        for (int i = 0; i < 8; ++i) s += smf[WS_U + i];
        atomicAdd(&g_wsum[wi], s);
    }

    // ---- AV: A = single-plane fp16 repack of C tiles; V via ldmatrix ----
    float oacc[4][4];
    #pragma unroll
    for (int nt = 0; nt < 4; ++nt)
        #pragma unroll
        for (int j = 0; j < 4; ++j) oacc[nt][j] = 0.0f;

    #pragma unroll
    for (int ch = 0; ch < 8; ++ch) {
        uint32_t ah0 = h2u(__floats2half2_rn(c[2 * ch][0],     c[2 * ch][1]));
        uint32_t ah1 = h2u(__floats2half2_rn(c[2 * ch][2],     c[2 * ch][3]));
        uint32_t ah2 = h2u(__floats2half2_rn(c[2 * ch + 1][0], c[2 * ch + 1][1]));
        uint32_t ah3 = h2u(__floats2half2_rn(c[2 * ch + 1][2], c[2 * ch + 1][3]));

        uint32_t v00, v01, v10, v11, v20, v21, v30, v31;
        LDSM_X4(v00, v01, v10, v11, vaddr + ch * 32);               // d rows 0-15
        LDSM_X4(v20, v21, v30, v31, vaddr + 16 * 272 + ch * 32);    // d rows 16-31
        MMA_F16(oacc[0][0], oacc[0][1], oacc[0][2], oacc[0][3],
                ah0, ah1, ah2, ah3, v00, v01);
        MMA_F16(oacc[1][0], oacc[1][1], oacc[1][2], oacc[1][3],
                ah0, ah1, ah2, ah3, v10, v11);
        MMA_F16(oacc[2][0], oacc[2][1], oacc[2][2], oacc[2][3],
                ah0, ah1, ah2, ah3, v20, v21);
        MMA_F16(oacc[3][0], oacc[3][1], oacc[3][2], oacc[3][3],
                ah0, ah1, ah2, ah3, v30, v31);
    }

    // ---- store y (ungated) as fp16: C-layout half2 pairs ----
    const size_t obase = ((size_t)(b * HW_) + (size_t)h * W_) * C_ + n * HD_;
    const int ocol = 2 * jl;
    #pragma unroll
    for (int nt = 0; nt < 4; ++nt) {
        __half2 p1 = __floats2half2_rn(oacc[nt][0], oacc[nt][1]);
        __half2 p2 = __floats2half2_rn(oacc[nt][2], oacc[nt][3]);
        *(__half2*)(g_yh + obase + (size_t)r1 * C_ + 8 * nt + ocol) = p1;
        *(__half2*)(g_yh + obase + (size_t)r2 * C_ + 8 * nt + ocol) = p2;
    }
}

// ---------------------------------------------------------------------------
// Gate: mean |attn| per window, global max, M = max(mean/max, 0.5).
// Resets g_wsum for the next graph replay.
// ---------------------------------------------------------------------------
__global__ void gate_kernel() {
    __shared__ float red[512];
    const int t = threadIdx.x;
    float mean = g_wsum[t] * (1.0f / 131072.0f);   // / (NH*W*W)
    g_wsum[t] = 0.0f;
    red[t] = mean;
    __syncthreads();
    for (int s = 256; s > 0; s >>= 1) {
        if (t < s) red[t] = fmaxf(red[t], red[t + s]);
        __syncthreads();
    }
    g_M[t] = fmaxf(mean / red[0], 0.5f);
}

// ---------------------------------------------------------------------------
// Blend: out = M * y + (1 - M) * res   (pure bandwidth)
// ---------------------------------------------------------------------------
__global__ __launch_bounds__(256) void blend_kernel(const float* __restrict__ resx,
                                                    float* __restrict__ out) {
    const int i  = blockIdx.x * 256 + threadIdx.x;   // float4 index
    const int wi = i >> 13;                          // / (W_*C_/4 = 8192)
    const float Mw   = g_M[wi];
    const float oneM = 1.0f - Mw;
    const __half2* yp = (const __half2*)g_yh + 2 * (size_t)i;
    float2 y01 = __half22float2(yp[0]);
    float2 y23 = __half22float2(yp[1]);
    float4 r = ((const float4*)resx)[i];
    float4 o;
    o.x = fmaf(Mw, y01.x, oneM * r.x);
    o.y = fmaf(Mw, y01.y, oneM * r.y);
    o.z = fmaf(Mw, y23.x, oneM * r.z);
    o.w = fmaf(Mw, y23.y, oneM * r.w);
    ((float4*)out)[i] = o;
}

// ---------------------------------------------------------------------------
extern "C" void kernel_launch(void* const* d_in, const int* in_sizes, int n_in,
                              void* d_out, int out_size) {
    (void)in_sizes; (void)n_in; (void)out_size;
    const float* qkv  = (const float*)d_in[0];
    const float* resx = (const float*)d_in[1];
    float* out = (float*)d_out;

    cudaFuncSetAttribute(fused_kernel, cudaFuncAttributeMaxDynamicSharedMemorySize,
                         FUSED_SMEM);

    fused_kernel<<<NCTA, 256, FUSED_SMEM>>>(qkv);
    gate_kernel<<<1, NWIN>>>();
    blend_kernel<<<(B_ * HW_ * C_ / 4) / 256, 256>>>(resx, out);
}

// round 12
// speedup vs baseline: 2.6998x; 1.0696x over previous
#include <cuda_runtime.h>
#include <cuda_fp16.h>
#include <math.h>
#include <cstdint>

// Problem constants
#define B_    4
#define H_    128
#define W_    128
#define C_    256
#define NH_   8
#define HD_   32
#define HW_   (H_ * W_)                 // 16384
#define NWIN  (B_ * H_)                 // 512
#define NCTA  (NWIN * NH_)              // 4096
#define QKV_STRIDE ((size_t)B_ * HW_ * C_)

// Scratch: ungated attention output y in fp16 (33.5 MB)
__device__ __align__(16) __half g_yh[(size_t)B_ * HW_ * C_];
__device__ float g_wsum[NWIN];
__device__ float g_M[NWIN];

// ---------------- fp16 m16n8k16 mma.sync (sm_80+ baseline) ----------------
#define MMA_F16(c0, c1, c2, c3, a0, a1, a2, a3, b0, b1) \
    asm volatile("mma.sync.aligned.m16n8k16.row.col.f32.f16.f16.f32 " \
        "{%0,%1,%2,%3}, {%4,%5,%6,%7}, {%8,%9}, {%0,%1,%2,%3};" \
        : "+f"(c0), "+f"(c1), "+f"(c2), "+f"(c3) \
        : "r"(a0), "r"(a1), "r"(a2), "r"(a3), "r"(b0), "r"(b1))

#define LDSM_X4(r0, r1, r2, r3, addr) \
    asm volatile("ldmatrix.sync.aligned.m8n8.x4.shared.b16 {%0,%1,%2,%3}, [%4];" \
        : "=r"(r0), "=r"(r1), "=r"(r2), "=r"(r3) : "r"(addr))

#define LDSM_X4T(r0, r1, r2, r3, addr) \
    asm volatile("ldmatrix.sync.aligned.m8n8.x4.trans.shared.b16 {%0,%1,%2,%3}, [%4];" \
        : "=r"(r0), "=r"(r1), "=r"(r2), "=r"(r3) : "r"(addr))

__device__ __forceinline__ uint32_t h2u(__half2 h) { return *(uint32_t*)&h; }
__device__ __forceinline__ uint32_t smem_u32(const void* p) {
    uint32_t a;
    asm("{ .reg .u64 t; cvta.to.shared.u64 t, %1; cvt.u32.u64 %0, t; }"
        : "=r"(a) : "l"(p));
    return a;
}

// ---------------- fused kernel smem layout (u32 word offsets) --------------
// QHP/KHP/VHP: [128 rows][20 stride] fp16x2 d-pairs (single plane each)
// SCT: float2[128] {sin(k*pi/127), cos(k*pi/127)}
#define QHP_U      0
#define KHP_U      2560
#define VHP_U      5120
#define SCT_U      7680
#define WS_U       7936
#define SMEM_WORDS 7944
#define FUSED_SMEM (SMEM_WORDS * 4)    // 31,776 bytes

#define A127 (3.14159265358979323846f / 127.0f)

// ---------------------------------------------------------------------------
// Fused kernel, per (window, head):
//   1. stage Q/K/V single-plane fp16 in smem, uniform [token][20] layout
//   2. init mma accumulators with the RPE bias (2*sin((k-q)pi/127) identity)
//   3. QK^T: 1 mma per k16 tile (bias pre-added via accumulator init)
//   4. |.| sums, per-row L2 norm (intra-warp), 1-cos packed straight to
//      half2 A-fragments (frees the fp32 tile registers before AV)
//   5. AV: V B-fragments via ldmatrix.x4.trans from the K-style layout
//   6. store ungated y as fp16 (gate M applied in blend kernel)
// ---------------------------------------------------------------------------
__global__ __launch_bounds__(256, 3) void fused_kernel(const float* __restrict__ qkv) {
    extern __shared__ uint32_t smu[];
    float* smf = (float*)smu;

    const int bx  = blockIdx.x;        // 0..4095
    const int wi  = bx >> 3;
    const int n   = bx & 7;
    const int b   = wi >> 7;
    const int h   = wi & 127;
    const int tid = threadIdx.x;
    const int wid = tid >> 5;
    const int lane = tid & 31;

    // sincos table for the RPE bias identity
    if (tid < 128) {
        float a = (float)tid * A127;
        smf[SCT_U + 2 * tid]     = sinf(a);
        smf[SCT_U + 2 * tid + 1] = cosf(a);
    }

    const float* qb = qkv + ((size_t)(b * HW_) + (size_t)h * W_) * C_ + n * HD_;
    const float* kb = qb + QKV_STRIDE;
    const float* vb = kb + QKV_STRIDE;

    // Stage Q/K/V (single fp16 plane each): packed d-pairs, row stride 20
    #pragma unroll
    for (int t = 0; t < 4; ++t) {
        int idx = tid + t * 256;       // 1024 float4 chunks
        int w   = idx >> 3;            // row 0..127
        int d4  = (idx & 7) << 2;      // 0,4,...,28
        float4 qv = *(const float4*)(qb + (size_t)w * C_ + d4);
        float4 kv = *(const float4*)(kb + (size_t)w * C_ + d4);
        float4 vv = *(const float4*)(vb + (size_t)w * C_ + d4);
        int base = w * 20 + (d4 >> 1);
        smu[QHP_U + base]     = h2u(__floats2half2_rn(qv.x, qv.y));
        smu[QHP_U + base + 1] = h2u(__floats2half2_rn(qv.z, qv.w));
        smu[KHP_U + base]     = h2u(__floats2half2_rn(kv.x, kv.y));
        smu[KHP_U + base + 1] = h2u(__floats2half2_rn(kv.z, kv.w));
        smu[VHP_U + base]     = h2u(__floats2half2_rn(vv.x, vv.y));
        smu[VHP_U + base + 1] = h2u(__floats2half2_rn(vv.z, vv.w));
    }
    __syncthreads();

    // ldmatrix per-lane base addresses (bytes)
    const uint32_t smb = smem_u32(smu);
    const uint32_t qrow  = 16 * wid + (lane & 7) + 8 * ((lane >> 3) & 1);
    const uint32_t qaddr = smb + 4 * (QHP_U + qrow * 20 + 4 * ((lane >> 4) & 1));
    const uint32_t krow  = (lane & 7) + 8 * ((lane >> 4) & 1);
    const uint32_t kaddr = smb + 4 * (KHP_U + krow * 20 + 4 * ((lane >> 3) & 1));
    // V (trans): token rows, tiles split (k0-7 / k8-15) by bit3, d-pair by bit4
    const uint32_t vrow  = (lane & 7) + 8 * ((lane >> 3) & 1);
    const uint32_t vaddr = smb + 4 * (VHP_U + vrow * 20 + 4 * ((lane >> 4) & 1));

    const int arow = 16 * wid + (lane >> 2);
    const int jl   = lane & 3;
    const int r1 = arow;
    const int r2 = arow + 8;

    // ---- init accumulators with RPE bias: bias = bs2*sin((col-row)*pi/127)
    const float bs2 = 0.2f * sinf((float)h * (3.14159265358979323846f / 128.0f));
    const float f1c = bs2 * cosf((float)r1 * A127);
    const float f1s = bs2 * sinf((float)r1 * A127);
    const float f2c = bs2 * cosf((float)r2 * A127);
    const float f2s = bs2 * sinf((float)r2 * A127);

    float c[16][4];
    #pragma unroll
    for (int nt = 0; nt < 16; ++nt) {
        const int col0 = 8 * nt + 2 * jl;
        float4 t = *(const float4*)(smf + SCT_U + 2 * col0);   // {s0,c0,s1,c1}
        c[nt][0] = t.x * f1c - t.y * f1s;
        c[nt][1] = t.z * f1c - t.w * f1s;
        c[nt][2] = t.x * f2c - t.y * f2s;
        c[nt][3] = t.z * f2c - t.w * f2s;
    }

    // ---- QK^T: warp wid -> rows 16*wid..16*wid+15, 2 chunks of k16 ----
    #pragma unroll
    for (int ch = 0; ch < 2; ++ch) {
        uint32_t qh0, qh1, qh2, qh3;
        LDSM_X4(qh0, qh1, qh2, qh3, qaddr + ch * 32);
        #pragma unroll
        for (int t = 0; t < 8; ++t) {
            uint32_t k00, k01, k10, k11;
            LDSM_X4(k00, k01, k10, k11, kaddr + t * 1280 + ch * 32);  // 16 rows * 80B
            MMA_F16(c[2*t][0], c[2*t][1], c[2*t][2], c[2*t][3],
                    qh0, qh1, qh2, qh3, k00, k01);
            MMA_F16(c[2*t+1][0], c[2*t+1][1], c[2*t+1][2], c[2*t+1][3],
                    qh0, qh1, qh2, qh3, k10, k11);
        }
    }

    // ---- epilogue: |.| sums + row sumsq (bias already inside c) ----
    float sq1 = 0.0f, sq2 = 0.0f, s_abs = 0.0f;
    #pragma unroll
    for (int nt = 0; nt < 16; ++nt) {
        sq1 += c[nt][0] * c[nt][0] + c[nt][1] * c[nt][1];
        sq2 += c[nt][2] * c[nt][2] + c[nt][3] * c[nt][3];
        s_abs += fabsf(c[nt][0]) + fabsf(c[nt][1]) + fabsf(c[nt][2]) + fabsf(c[nt][3]);
    }
    sq1 += __shfl_xor_sync(0xffffffffu, sq1, 1);
    sq1 += __shfl_xor_sync(0xffffffffu, sq1, 2);
    sq2 += __shfl_xor_sync(0xffffffffu, sq2, 1);
    sq2 += __shfl_xor_sync(0xffffffffu, sq2, 2);
    #pragma unroll
    for (int m = 16; m; m >>= 1)
        s_abs += __shfl_xor_sync(0xffffffffu, s_abs, m);
    if (lane == 0) smf[WS_U + wid] = s_abs;

    // ---- transform: pack 1-cos(v*(pi/2)/norm) straight to half2 A-frags ----
    uint32_t aw[16][2];
    {
        const float inv1 = 1.57079632679489662f / fmaxf(sqrtf(sq1), 1e-12f);
        const float inv2 = 1.57079632679489662f / fmaxf(sqrtf(sq2), 1e-12f);
        #pragma unroll
        for (int nt = 0; nt < 16; ++nt) {
            float t0 = 1.0f - __cosf(c[nt][0] * inv1);
            float t1 = 1.0f - __cosf(c[nt][1] * inv1);
            float t2 = 1.0f - __cosf(c[nt][2] * inv2);
            float t3 = 1.0f - __cosf(c[nt][3] * inv2);
            aw[nt][0] = h2u(__floats2half2_rn(t0, t1));
            aw[nt][1] = h2u(__floats2half2_rn(t2, t3));
        }
    }

    __syncthreads();   // WS visible
    if (tid == 0) {
        float s = 0.0f;
        #pragma unroll
        for (int i = 0; i < 8; ++i) s += smf[WS_U + i];
        atomicAdd(&g_wsum[wi], s);
    }

    // ---- AV: A-frags from aw, V B-frags via ldmatrix.trans ----
    float oacc[4][4];
    #pragma unroll
    for (int nt = 0; nt < 4; ++nt)
        #pragma unroll
        for (int j = 0; j < 4; ++j) oacc[nt][j] = 0.0f;

    #pragma unroll
    for (int ch = 0; ch < 8; ++ch) {
        const uint32_t ah0 = aw[2 * ch][0];
        const uint32_t ah1 = aw[2 * ch][1];
        const uint32_t ah2 = aw[2 * ch + 1][0];
        const uint32_t ah3 = aw[2 * ch + 1][1];

        // trans tiles: r0=(k0-7,dg0) r1=(k8-15,dg0) r2=(k0-7,dg1) r3=(k8-15,dg1)
        uint32_t v00, v01, v02, v03, v10, v11, v12, v13;
        LDSM_X4T(v00, v01, v02, v03, vaddr + ch * 1280);        // d 0-15
        LDSM_X4T(v10, v11, v12, v13, vaddr + ch * 1280 + 32);   // d 16-31
        MMA_F16(oacc[0][0], oacc[0][1], oacc[0][2], oacc[0][3],
                ah0, ah1, ah2, ah3, v00, v01);
        MMA_F16(oacc[1][0], oacc[1][1], oacc[1][2], oacc[1][3],
                ah0, ah1, ah2, ah3, v02, v03);
        MMA_F16(oacc[2][0], oacc[2][1], oacc[2][2], oacc[2][3],
                ah0, ah1, ah2, ah3, v10, v11);
        MMA_F16(oacc[3][0], oacc[3][1], oacc[3][2], oacc[3][3],
                ah0, ah1, ah2, ah3, v12, v13);
    }

    // ---- store y (ungated) as fp16: C-layout half2 pairs ----
    const size_t obase = ((size_t)(b * HW_) + (size_t)h * W_) * C_ + n * HD_;
    const int ocol = 2 * jl;
    #pragma unroll
    for (int nt = 0; nt < 4; ++nt) {
        __half2 p1 = __floats2half2_rn(oacc[nt][0], oacc[nt][1]);
        __half2 p2 = __floats2half2_rn(oacc[nt][2], oacc[nt][3]);
        *(__half2*)(g_yh + obase + (size_t)r1 * C_ + 8 * nt + ocol) = p1;
        *(__half2*)(g_yh + obase + (size_t)r2 * C_ + 8 * nt + ocol) = p2;
    }
}

// ---------------------------------------------------------------------------
// Gate: mean |attn| per window, global max, M = max(mean/max, 0.5).
// Resets g_wsum for the next graph replay.
// ---------------------------------------------------------------------------
__global__ void gate_kernel() {
    __shared__ float red[512];
    const int t = threadIdx.x;
    float mean = g_wsum[t] * (1.0f / 131072.0f);   // / (NH*W*W)
    g_wsum[t] = 0.0f;
    red[t] = mean;
    __syncthreads();
    for (int s = 256; s > 0; s >>= 1) {
        if (t < s) red[t] = fmaxf(red[t], red[t + s]);
        __syncthreads();
    }
    g_M[t] = fmaxf(mean / red[0], 0.5f);
}

// ---------------------------------------------------------------------------
// Blend: out = M * y + (1 - M) * res   (pure bandwidth)
// ---------------------------------------------------------------------------
__global__ __launch_bounds__(256) void blend_kernel(const float* __restrict__ resx,
                                                    float* __restrict__ out) {
    const int i  = blockIdx.x * 256 + threadIdx.x;   // float4 index
    const int wi = i >> 13;                          // / (W_*C_/4 = 8192)
    const float Mw   = g_M[wi];
    const float oneM = 1.0f - Mw;
    const __half2* yp = (const __half2*)g_yh + 2 * (size_t)i;
    float2 y01 = __half22float2(yp[0]);
    float2 y23 = __half22float2(yp[1]);
    float4 r = ((const float4*)resx)[i];
    float4 o;
    o.x = fmaf(Mw, y01.x, oneM * r.x);
    o.y = fmaf(Mw, y01.y, oneM * r.y);
    o.z = fmaf(Mw, y23.x, oneM * r.z);
    o.w = fmaf(Mw, y23.y, oneM * r.w);
    ((float4*)out)[i] = o;
}

// ---------------------------------------------------------------------------
extern "C" void kernel_launch(void* const* d_in, const int* in_sizes, int n_in,
                              void* d_out, int out_size) {
    (void)in_sizes; (void)n_in; (void)out_size;
    const float* qkv  = (const float*)d_in[0];
    const float* resx = (const float*)d_in[1];
    float* out = (float*)d_out;

    cudaFuncSetAttribute(fused_kernel, cudaFuncAttributeMaxDynamicSharedMemorySize,
                         FUSED_SMEM);

    fused_kernel<<<NCTA, 256, FUSED_SMEM>>>(qkv);
    gate_kernel<<<1, NWIN>>>();
    blend_kernel<<<(B_ * HW_ * C_ / 4) / 256, 256>>>(resx, out);
}